// round 14
// baseline (speedup 1.0000x reference)
#include <cuda_runtime.h>
#include <cuda_bf16.h>
#include <math.h>
#include <stdint.h>

#define NN 100000
#define NE 1600000
#define DF 128
#define NG 512
#define DH 256
#define SB ((NN + 255) / 256)   // 391 scan blocks

// ------------------- scratch (__device__ globals; no allocation) -------------------
static __device__ int   g_cnt[NN];
static __device__ int   g_wptr[NN];
static __device__ int   g_rowptr[NN + 1];
static __device__ int   g_bsum[512];
static __device__ int   g_boff[512];
static __device__ int   g_col[NE];
static __device__ float g_dinv[NN];
static __device__ __align__(16) __nv_bfloat16 g_xhi[(size_t)NN * DF]; // split activations
static __device__ __align__(16) __nv_bfloat16 g_xlo[(size_t)NN * DF];
static __device__ __align__(16) float g_h[(size_t)NN * DF];           // conv pre-agg (fp32)
static __device__ __align__(16) __nv_bfloat16 g_Whi[DF * DF];  // [n][k]
static __device__ __align__(16) __nv_bfloat16 g_Wlo[DF * DF];  // [n][k]
static __device__ __align__(16) float g_dvec[DF];
static __device__ float g_bnsum[3 * DF];
static __device__ float g_bnsq [3 * DF];
static __device__ __align__(16) float g_pool[NG * DF];
static __device__ float g_gcnt[NG];
static __device__ float g_h0[NG * DH];
static __device__ float g_h1[NG * DH];
static __device__ float g_sq[4 * DH];      // s0,q0,s1,q1

// ------------------- one-shot init -------------------
#define INIT_TOT (NN + 3 * DF * 2 + NG * DF + NG + 4 * DH)
__global__ void k_init() {
    int i = blockIdx.x * blockDim.x + threadIdx.x;
    if (i < NN) { g_cnt[i] = 0; return; }
    i -= NN;
    if (i < 3 * DF) { g_bnsum[i] = 0.f; return; }
    i -= 3 * DF;
    if (i < 3 * DF) { g_bnsq[i] = 0.f; return; }
    i -= 3 * DF;
    if (i < NG * DF) { g_pool[i] = 0.f; return; }
    i -= NG * DF;
    if (i < NG) { g_gcnt[i] = 0.f; return; }
    i -= NG;
    if (i < 4 * DH) g_sq[i] = 0.f;
}

// ------------------- CSR build -------------------
__global__ void k_hist(const int* __restrict__ dst) {
    int e = blockIdx.x * blockDim.x + threadIdx.x;
    if (e < NE) atomicAdd(&g_cnt[dst[e]], 1);
}
__global__ void __launch_bounds__(256) k_scanA() {
    __shared__ int s[256];
    int t = threadIdx.x;
    int i = blockIdx.x * 256 + t;
    int v = (i < NN) ? g_cnt[i] : 0;
    if (i < NN) g_dinv[i] = rsqrtf((float)v + 1.0f);
    s[t] = v;
    __syncthreads();
#pragma unroll
    for (int off = 1; off < 256; off <<= 1) {
        int u = (t >= off) ? s[t - off] : 0;
        __syncthreads();
        s[t] += u;
        __syncthreads();
    }
    if (i < NN) g_rowptr[i] = s[t] - v;
    if (t == 255) g_bsum[blockIdx.x] = s[255];
}
__global__ void __launch_bounds__(512) k_scanB() {
    __shared__ int s[512];
    int t = threadIdx.x;
    int v = (t < SB) ? g_bsum[t] : 0;
    s[t] = v;
    __syncthreads();
#pragma unroll
    for (int off = 1; off < 512; off <<= 1) {
        int u = (t >= off) ? s[t - off] : 0;
        __syncthreads();
        s[t] += u;
        __syncthreads();
    }
    g_boff[t] = s[t] - v;
    if (t == 0) g_rowptr[NN] = NE;
}
__global__ void __launch_bounds__(256) k_scanC() {
    int i = blockIdx.x * 256 + threadIdx.x;
    if (i < NN) {
        int r = g_rowptr[i] + g_boff[blockIdx.x];
        g_rowptr[i] = r;
        g_wptr[i]   = r;
    }
}
__global__ void k_fill(const int* __restrict__ src, const int* __restrict__ dst) {
    int e = blockIdx.x * blockDim.x + threadIdx.x;
    if (e < NE) {
        int v = dst[e];
        int pos = atomicAdd(&g_wptr[v], 1);
        g_col[pos] = src[e];
    }
}

// ------------------- mma.sync helpers -------------------
__device__ __forceinline__ uint32_t smem_u32(const void* p) {
    uint32_t a;
    asm("{ .reg .u64 t; cvta.to.shared.u64 t, %1; cvt.u32.u64 %0, t; }" : "=r"(a) : "l"(p));
    return a;
}
#define LDMX4(r, addr) \
    asm volatile("ldmatrix.sync.aligned.m8n8.x4.shared.b16 {%0,%1,%2,%3}, [%4];" \
        : "=r"((r)[0]), "=r"((r)[1]), "=r"((r)[2]), "=r"((r)[3]) : "r"(addr))
#define MMA_BF16(c, a, b0, b1) \
    asm volatile("mma.sync.aligned.m16n8k16.row.col.f32.bf16.bf16.f32 " \
        "{%0,%1,%2,%3}, {%4,%5,%6,%7}, {%8,%9}, {%0,%1,%2,%3};" \
        : "+f"((c)[0]), "+f"((c)[1]), "+f"((c)[2]), "+f"((c)[3]) \
        : "r"((a)[0]), "r"((a)[1]), "r"((a)[2]), "r"((a)[3]), "r"(b0), "r"(b1))

__device__ __forceinline__ void split8(const float* f, uint4& hi, uint4& lo) {
    uint32_t h[4], l[4];
#pragma unroll
    for (int p = 0; p < 4; p++) {
        __nv_bfloat16 h0 = __float2bfloat16(f[2 * p]);
        __nv_bfloat16 h1 = __float2bfloat16(f[2 * p + 1]);
        __nv_bfloat16 l0 = __float2bfloat16(f[2 * p]     - __bfloat162float(h0));
        __nv_bfloat16 l1 = __float2bfloat16(f[2 * p + 1] - __bfloat162float(h1));
        h[p] = (uint32_t)__bfloat16_as_ushort(h0) | ((uint32_t)__bfloat16_as_ushort(h1) << 16);
        l[p] = (uint32_t)__bfloat16_as_ushort(l0) | ((uint32_t)__bfloat16_as_ushort(l1) << 16);
    }
    hi = make_uint4(h[0], h[1], h[2], h[3]);
    lo = make_uint4(l[0], l[1], l[2], l[3]);
}

// ------------------- tensor-core GEMM: C[M,128] = A @ W + dvec ----------------------
// Tile M=64 x N=128 x K=128. SMEM 96KB -> 2 CTAs/SM. 8 warps: 2m x 4n, warp m32 x n32.
// A source: either fp32 (Af, split in-kernel) or pre-split bf16 (Ahi/Alo).
#define SMO_AHI 0
#define SMO_ALO 16384
#define SMO_BHI 32768
#define SMO_BLO 65536
#define SM_TOT  98304

__global__ void __launch_bounds__(256) k_mmagemm(
    const float* __restrict__ Af,
    const __nv_bfloat16* __restrict__ Ahi, const __nv_bfloat16* __restrict__ Alo,
    const __nv_bfloat16* __restrict__ Bhi, const __nv_bfloat16* __restrict__ Blo,
    const float* __restrict__ dvec, float* __restrict__ C, int M)
{
    extern __shared__ char sm[];
    uint32_t sbase = smem_u32(sm);
    int tid = threadIdx.x, lane = tid & 31, wid = tid >> 5;
    int warpM = wid & 1, warpN = wid >> 1;   // 2 x 4
    int row0 = blockIdx.x * 64;

    // stage B (bf16 [n][k]) with XOR swizzle
    for (int i = tid; i < 2048; i += 256) {
        int n = i >> 4, c = i & 15;
        uint32_t off = n * 256 + (uint32_t)((c ^ (n & 7)) << 4);
        *(uint4*)(sm + SMO_BHI + off) = *(const uint4*)(Bhi + n * 128 + c * 8);
        *(uint4*)(sm + SMO_BLO + off) = *(const uint4*)(Blo + n * 128 + c * 8);
    }
    if (Af) {
        // fp32 A: split in-kernel (64 rows)
        for (int i = tid; i < 1024; i += 256) {
            int m = i >> 4, c = i & 15;
            int row = row0 + m;
            float f[8];
            if (row < M) {
                float4 f0 = *(const float4*)(Af + (size_t)row * 128 + c * 8);
                float4 f1 = *(const float4*)(Af + (size_t)row * 128 + c * 8 + 4);
                f[0] = f0.x; f[1] = f0.y; f[2] = f0.z; f[3] = f0.w;
                f[4] = f1.x; f[5] = f1.y; f[6] = f1.z; f[7] = f1.w;
            } else {
#pragma unroll
                for (int p = 0; p < 8; p++) f[p] = 0.f;
            }
            uint4 hi, lo;
            split8(f, hi, lo);
            uint32_t off = m * 256 + (uint32_t)((c ^ (m & 7)) << 4);
            *(uint4*)(sm + SMO_AHI + off) = hi;
            *(uint4*)(sm + SMO_ALO + off) = lo;
        }
    } else {
        // pre-split bf16 A: straight copies
        const uint4 Z = make_uint4(0, 0, 0, 0);
        for (int i = tid; i < 1024; i += 256) {
            int m = i >> 4, c = i & 15;
            int row = row0 + m;
            uint32_t off = m * 256 + (uint32_t)((c ^ (m & 7)) << 4);
            *(uint4*)(sm + SMO_AHI + off) =
                (row < M) ? *(const uint4*)(Ahi + (size_t)row * 128 + c * 8) : Z;
            *(uint4*)(sm + SMO_ALO + off) =
                (row < M) ? *(const uint4*)(Alo + (size_t)row * 128 + c * 8) : Z;
        }
    }
    __syncthreads();

    float acc[2][4][4];
#pragma unroll
    for (int i = 0; i < 2; i++)
#pragma unroll
        for (int j = 0; j < 4; j++)
#pragma unroll
            for (int q = 0; q < 4; q++) acc[i][j][q] = 0.f;

    int a_mrow0 = warpM * 32 + (lane & 15);
    int a_kadd  = (lane >> 4) << 3;
    int b_nadd  = (lane & 7) + ((lane >> 4) << 3);
    int b_kadd  = ((lane >> 3) & 1) << 3;

#pragma unroll
    for (int ks = 0; ks < 8; ks++) {
        int K0 = ks * 16;
        uint32_t ahi[2][4], alo[2][4];
#pragma unroll
        for (int fm = 0; fm < 2; fm++) {
            int mrow = a_mrow0 + fm * 16;
            int kk = K0 + a_kadd;
            uint32_t off = mrow * 256 + (uint32_t)((((kk >> 3) ^ (mrow & 7)) << 4));
            LDMX4(ahi[fm], sbase + SMO_AHI + off);
            LDMX4(alo[fm], sbase + SMO_ALO + off);
        }
#pragma unroll
        for (int nb = 0; nb < 2; nb++) {
            int nrow = warpN * 32 + nb * 16 + b_nadd;
            int kk = K0 + b_kadd;
            uint32_t off = nrow * 256 + (uint32_t)((((kk >> 3) ^ (nrow & 7)) << 4));
            uint32_t bhi[4], blo[4];
            LDMX4(bhi, sbase + SMO_BHI + off);
            LDMX4(blo, sbase + SMO_BLO + off);
#pragma unroll
            for (int fm = 0; fm < 2; fm++) {
                MMA_BF16(acc[fm][nb * 2 + 0], ahi[fm], bhi[0], bhi[1]);
                MMA_BF16(acc[fm][nb * 2 + 1], ahi[fm], bhi[2], bhi[3]);
            }
#pragma unroll
            for (int fm = 0; fm < 2; fm++) {
                MMA_BF16(acc[fm][nb * 2 + 0], ahi[fm], blo[0], blo[1]);
                MMA_BF16(acc[fm][nb * 2 + 1], ahi[fm], blo[2], blo[3]);
            }
#pragma unroll
            for (int fm = 0; fm < 2; fm++) {
                MMA_BF16(acc[fm][nb * 2 + 0], alo[fm], bhi[0], bhi[1]);
                MMA_BF16(acc[fm][nb * 2 + 1], alo[fm], bhi[2], bhi[3]);
            }
        }
    }

#pragma unroll
    for (int fm = 0; fm < 2; fm++) {
#pragma unroll
        for (int nf = 0; nf < 4; nf++) {
            int r = row0 + warpM * 32 + fm * 16 + (lane >> 2);
            int col = warpN * 32 + nf * 8 + (lane & 3) * 2;
            float d0 = dvec ? dvec[col] : 0.f;
            float d1 = dvec ? dvec[col + 1] : 0.f;
            if (r < M)
                *(float2*)(C + (size_t)r * 128 + col) =
                    make_float2(acc[fm][nf][0] + d0, acc[fm][nf][1] + d1);
            if (r + 8 < M)
                *(float2*)(C + (size_t)(r + 8) * 128 + col) =
                    make_float2(acc[fm][nf][2] + d0, acc[fm][nf][3] + d1);
        }
    }
}

// ------------------- W prep with in-block BN affine (bnsum==null -> identity) -------
__global__ void k_wprep(const float* __restrict__ W,
                        const float* __restrict__ bnsum, const float* __restrict__ bnsq,
                        const float* __restrict__ gamma, const float* __restrict__ beta) {
    const float invN = 1.0f / NN;
    if (blockIdx.x < 64) {
        int i = blockIdx.x * 256 + threadIdx.x;   // 0..16383
        int n = i >> 7, k = i & 127;
        float a = 1.0f;
        if (bnsum) {
            float m   = bnsum[k] * invN;
            float var = bnsq[k] * invN - m * m;
            a = gamma[k] * rsqrtf(var + 1e-5f);
        }
        float w = a * W[k * DF + n];
        __nv_bfloat16 hi = __float2bfloat16(w);
        __nv_bfloat16 lo = __float2bfloat16(w - __bfloat162float(hi));
        g_Whi[n * DF + k] = hi;
        g_Wlo[n * DF + k] = lo;
    } else if (bnsum) {
        __shared__ float sc[DF];
        int j = threadIdx.x;
        if (j < DF) {
            float m   = bnsum[j] * invN;
            float var = bnsq[j] * invN - m * m;
            float a   = gamma[j] * rsqrtf(var + 1e-5f);
            sc[j] = beta[j] - a * m;
        }
        __syncthreads();
        if (j < DF) {
            float s = 0.f;
#pragma unroll 8
            for (int k = 0; k < DF; k++) s = fmaf(sc[k], W[k * DF + j], s);
            g_dvec[j] = s;
        }
    }
}

// ------------------- GCN aggregation + bias + relu + BN stats; writes split bf16 ----
__global__ void __launch_bounds__(256) k_agg(
    const float* __restrict__ h, const float* __restrict__ bias,
    __nv_bfloat16* __restrict__ xhi, __nv_bfloat16* __restrict__ xlo,
    float* __restrict__ bnsum, float* __restrict__ bnsq)
{
    __shared__ float bs[DF], bq[DF];
    int tid = threadIdx.x;
    if (tid < DF) { bs[tid] = 0.f; bq[tid] = 0.f; }
    __syncthreads();

    int lane = tid & 31;
    int w    = tid >> 5;
    int warpId = blockIdx.x * (blockDim.x >> 5) + w;
    int nW     = gridDim.x * (blockDim.x >> 5);

    float4 bv = *(const float4*)(bias + lane * 4);
    float ls0 = 0, ls1 = 0, ls2 = 0, ls3 = 0;
    float lq0 = 0, lq1 = 0, lq2 = 0, lq3 = 0;

    for (int v = warpId; v < NN; v += nW) {
        float dv = g_dinv[v];
        float4 hv = *((const float4*)(h + (size_t)v * DF) + lane);
        float ax = hv.x * dv, ay = hv.y * dv, az = hv.z * dv, aw = hv.w * dv;

        int beg = g_rowptr[v], end = g_rowptr[v + 1];
        for (int e0 = beg; e0 < end; e0 += 32) {
            int idx = e0 + lane;
            int   sl = (idx < end) ? g_col[idx]  : 0;
            float dl = (idx < end) ? g_dinv[sl]  : 0.f;
            int m = end - e0; if (m > 32) m = 32;
            for (int j = 0; j < m; j++) {
                int   sj  = __shfl_sync(0xffffffffu, sl, j);
                float dsj = __shfl_sync(0xffffffffu, dl, j);
                float4 hs = *((const float4*)(h + (size_t)sj * DF) + lane);
                ax = fmaf(hs.x, dsj, ax);
                ay = fmaf(hs.y, dsj, ay);
                az = fmaf(hs.z, dsj, az);
                aw = fmaf(hs.w, dsj, aw);
            }
        }
        float ox = fmaxf(fmaf(ax, dv, bv.x), 0.f);
        float oy = fmaxf(fmaf(ay, dv, bv.y), 0.f);
        float oz = fmaxf(fmaf(az, dv, bv.z), 0.f);
        float ow = fmaxf(fmaf(aw, dv, bv.w), 0.f);
        // split store
        __nv_bfloat16 hx = __float2bfloat16(ox), hy = __float2bfloat16(oy);
        __nv_bfloat16 hz = __float2bfloat16(oz), hw = __float2bfloat16(ow);
        __nv_bfloat16 lx = __float2bfloat16(ox - __bfloat162float(hx));
        __nv_bfloat16 ly = __float2bfloat16(oy - __bfloat162float(hy));
        __nv_bfloat16 lz = __float2bfloat16(oz - __bfloat162float(hz));
        __nv_bfloat16 lw = __float2bfloat16(ow - __bfloat162float(hw));
        uint2 uh = make_uint2(
            (uint32_t)__bfloat16_as_ushort(hx) | ((uint32_t)__bfloat16_as_ushort(hy) << 16),
            (uint32_t)__bfloat16_as_ushort(hz) | ((uint32_t)__bfloat16_as_ushort(hw) << 16));
        uint2 ul = make_uint2(
            (uint32_t)__bfloat16_as_ushort(lx) | ((uint32_t)__bfloat16_as_ushort(ly) << 16),
            (uint32_t)__bfloat16_as_ushort(lz) | ((uint32_t)__bfloat16_as_ushort(lw) << 16));
        *((uint2*)(xhi + (size_t)v * DF + lane * 4)) = uh;
        *((uint2*)(xlo + (size_t)v * DF + lane * 4)) = ul;

        ls0 += ox; lq0 += ox * ox;
        ls1 += oy; lq1 += oy * oy;
        ls2 += oz; lq2 += oz * oz;
        ls3 += ow; lq3 += ow * ow;
    }
    atomicAdd(&bs[lane * 4 + 0], ls0); atomicAdd(&bq[lane * 4 + 0], lq0);
    atomicAdd(&bs[lane * 4 + 1], ls1); atomicAdd(&bq[lane * 4 + 1], lq1);
    atomicAdd(&bs[lane * 4 + 2], ls2); atomicAdd(&bq[lane * 4 + 2], lq2);
    atomicAdd(&bs[lane * 4 + 3], ls3); atomicAdd(&bq[lane * 4 + 3], lq3);
    __syncthreads();
    if (tid < DF) {
        atomicAdd(&bnsum[tid], bs[tid]);
        atomicAdd(&bnsq[tid],  bq[tid]);
    }
}

// ------------------- global_add_pool (reads split activations) ----------------------
__global__ void k_pool(const __nv_bfloat16* __restrict__ xhi,
                       const __nv_bfloat16* __restrict__ xlo,
                       const int* __restrict__ batch) {
    int lane = threadIdx.x & 31;
    int w    = (blockIdx.x * blockDim.x + threadIdx.x) >> 5;
    int nW   = (gridDim.x * blockDim.x) >> 5;
    int C    = (NN + nW - 1) / nW;
    int beg = w * C;
    int end = beg + C; if (end > NN) end = NN;
    if (beg >= end) return;

    float a0 = 0, a1 = 0, a2 = 0, a3 = 0, cntf = 0;
    int cur = batch[beg];
    for (int v = beg; v < end; v++) {
        int g = batch[v];
        if (g != cur) {
            atomicAdd(&g_pool[cur * DF + lane * 4 + 0], a0);
            atomicAdd(&g_pool[cur * DF + lane * 4 + 1], a1);
            atomicAdd(&g_pool[cur * DF + lane * 4 + 2], a2);
            atomicAdd(&g_pool[cur * DF + lane * 4 + 3], a3);
            if (lane == 0) atomicAdd(&g_gcnt[cur], cntf);
            a0 = a1 = a2 = a3 = 0.f; cntf = 0.f; cur = g;
        }
        uint2 uh = *((const uint2*)(xhi + (size_t)v * DF + lane * 4));
        uint2 ul = *((const uint2*)(xlo + (size_t)v * DF + lane * 4));
        float2 h01 = __bfloat1622float2(*(__nv_bfloat162*)&uh.x);
        float2 h23 = __bfloat1622float2(*(__nv_bfloat162*)&uh.y);
        float2 l01 = __bfloat1622float2(*(__nv_bfloat162*)&ul.x);
        float2 l23 = __bfloat1622float2(*(__nv_bfloat162*)&ul.y);
        a0 += h01.x + l01.x; a1 += h01.y + l01.y;
        a2 += h23.x + l23.x; a3 += h23.y + l23.y;
        cntf += 1.f;
    }
    atomicAdd(&g_pool[cur * DF + lane * 4 + 0], a0);
    atomicAdd(&g_pool[cur * DF + lane * 4 + 1], a1);
    atomicAdd(&g_pool[cur * DF + lane * 4 + 2], a2);
    atomicAdd(&g_pool[cur * DF + lane * 4 + 3], a3);
    if (lane == 0) atomicAdd(&g_gcnt[cur], cntf);
}

// ------------------- head (BN affine computed in-block) -------------------
__global__ void __launch_bounds__(256) k_hg0(
    const float* __restrict__ Wh0, const float* __restrict__ bh0,
    const float* __restrict__ bnsum, const float* __restrict__ bnsq,
    const float* __restrict__ gamma, const float* __restrict__ beta) {
    __shared__ float sx[DF];
    int g = blockIdx.x, j = threadIdx.x;
    if (j < DF) {
        const float invN = 1.0f / NN;
        float m   = bnsum[j] * invN;
        float var = bnsq[j] * invN - m * m;
        float a   = gamma[j] * rsqrtf(var + 1e-5f);
        float c   = beta[j] - a * m;
        sx[j] = a * g_pool[g * DF + j] + c * g_gcnt[g];
    }
    __syncthreads();
    float acc = bh0[j];
#pragma unroll 8
    for (int k = 0; k < DF; k++) acc = fmaf(sx[k], Wh0[k * DH + j], acc);
    float v = fmaxf(acc, 0.f);
    g_h0[g * DH + j] = v;
    atomicAdd(&g_sq[j], v);
    atomicAdd(&g_sq[DH + j], v * v);
}
__global__ void __launch_bounds__(256) k_hg1(
    const float* __restrict__ Wh1, const float* __restrict__ bh1,
    const float* __restrict__ gamma, const float* __restrict__ beta) {
    __shared__ float sx[DH];
    int g = blockIdx.x, j = threadIdx.x;
    {
        const float invG = 1.0f / NG;
        float m   = g_sq[j] * invG;
        float var = g_sq[DH + j] * invG - m * m;
        float a   = gamma[j] * rsqrtf(var + 1e-5f);
        float c   = beta[j] - a * m;
        sx[j] = a * g_h0[g * DH + j] + c;
    }
    __syncthreads();
    float acc = bh1[j];
#pragma unroll 8
    for (int k = 0; k < DH; k++) acc = fmaf(sx[k], Wh1[k * DH + j], acc);
    float v = fmaxf(acc, 0.f);
    g_h1[g * DH + j] = v;
    atomicAdd(&g_sq[2 * DH + j], v);
    atomicAdd(&g_sq[3 * DH + j], v * v);
}
__global__ void __launch_bounds__(256) k_final(
    const float* __restrict__ Wout, const float* __restrict__ bout,
    const float* __restrict__ gamma, const float* __restrict__ beta,
    float* __restrict__ out) {
    __shared__ float red[DH];
    int g = blockIdx.x, t = threadIdx.x;
    {
        const float invG = 1.0f / NG;
        float m   = g_sq[2 * DH + t] * invG;
        float var = g_sq[3 * DH + t] * invG - m * m;
        float a   = gamma[t] * rsqrtf(var + 1e-5f);
        float c   = beta[t] - a * m;
        red[t] = (a * g_h1[g * DH + t] + c) * Wout[t];
    }
    __syncthreads();
    for (int o = DH / 2; o > 0; o >>= 1) {
        if (t < o) red[t] += red[t + o];
        __syncthreads();
    }
    if (t == 0) out[g] = red[0] + bout[0];
}

// ------------------- launch -------------------
extern "C" void kernel_launch(void* const* d_in, const int* in_sizes, int n_in,
                              void* d_out, int out_size) {
    const float* x   = (const float*)d_in[0];
    const int*   ei  = (const int*)d_in[1];
    const int*   bat = (const int*)d_in[2];
    const float* Wc  = (const float*)d_in[3];
    const float* bc  = (const float*)d_in[4];
    const float* gc  = (const float*)d_in[5];
    const float* bec = (const float*)d_in[6];
    const float* Wh0 = (const float*)d_in[7];
    const float* bh0 = (const float*)d_in[8];
    const float* gh0 = (const float*)d_in[9];
    const float* beh0= (const float*)d_in[10];
    const float* Wh1 = (const float*)d_in[11];
    const float* bh1 = (const float*)d_in[12];
    const float* gh1 = (const float*)d_in[13];
    const float* beh1= (const float*)d_in[14];
    const float* Wout= (const float*)d_in[15];
    const float* bout= (const float*)d_in[16];
    float* out = (float*)d_out;

    const int* src = ei;
    const int* dst = ei + NE;

    float *p_h, *p_dvec, *p_bnsum, *p_bnsq;
    __nv_bfloat16 *p_Whi, *p_Wlo, *p_xhi, *p_xlo;
    cudaGetSymbolAddress((void**)&p_xhi,  g_xhi);
    cudaGetSymbolAddress((void**)&p_xlo,  g_xlo);
    cudaGetSymbolAddress((void**)&p_h,    g_h);
    cudaGetSymbolAddress((void**)&p_Whi,  g_Whi);
    cudaGetSymbolAddress((void**)&p_Wlo,  g_Wlo);
    cudaGetSymbolAddress((void**)&p_dvec, g_dvec);
    cudaGetSymbolAddress((void**)&p_bnsum,g_bnsum);
    cudaGetSymbolAddress((void**)&p_bnsq, g_bnsq);

    cudaFuncSetAttribute(k_mmagemm, cudaFuncAttributeMaxDynamicSharedMemorySize, SM_TOT);

    static cudaStream_t s_side = nullptr;
    static cudaEvent_t  e_fork = nullptr, e_join = nullptr;
    if (!s_side) {
        cudaStreamCreateWithFlags(&s_side, cudaStreamNonBlocking);
        cudaEventCreateWithFlags(&e_fork, cudaEventDisableTiming);
        cudaEventCreateWithFlags(&e_join, cudaEventDisableTiming);
    }

    const int T = 256;
    const int gemmBlocks = (NN + 63) / 64;

    // ---- init (main stream), then fork CSR build onto side stream ----
    k_init<<<(INIT_TOT + T - 1) / T, T>>>();
    cudaEventRecord(e_fork, 0);
    cudaStreamWaitEvent(s_side, e_fork, 0);
    k_hist <<<(NE + T - 1) / T, T, 0, s_side>>>(dst);
    k_scanA<<<SB, 256, 0, s_side>>>();
    k_scanB<<<1, 512, 0, s_side>>>();
    k_scanC<<<SB, 256, 0, s_side>>>();
    k_fill <<<(NE + T - 1) / T, T, 0, s_side>>>(src, dst);
    cudaEventRecord(e_join, s_side);

    // ---- main stream: layer-0 wprep + GEMM overlap CSR build ----
    k_wprep<<<65, T>>>(Wc, nullptr, nullptr, nullptr, nullptr);
    k_mmagemm<<<gemmBlocks, T, SM_TOT>>>(x, nullptr, nullptr, p_Whi, p_Wlo, nullptr, p_h, NN);
    cudaStreamWaitEvent(0, e_join, 0);
    k_agg<<<2048, T>>>(p_h, bc, p_xhi, p_xlo, p_bnsum, p_bnsq);

    // ---- conv layer 1 (pre-split A) ----
    k_wprep<<<65, T>>>(Wc + DF * DF, p_bnsum, p_bnsq, gc, bec);
    k_mmagemm<<<gemmBlocks, T, SM_TOT>>>(nullptr, p_xhi, p_xlo, p_Whi, p_Wlo, p_dvec, p_h, NN);
    k_agg<<<2048, T>>>(p_h, bc + DF, p_xhi, p_xlo, p_bnsum + DF, p_bnsq + DF);

    // ---- conv layer 2 ----
    k_wprep<<<65, T>>>(Wc + 2 * DF * DF, p_bnsum + DF, p_bnsq + DF, gc + DF, bec + DF);
    k_mmagemm<<<gemmBlocks, T, SM_TOT>>>(nullptr, p_xhi, p_xlo, p_Whi, p_Wlo, p_dvec, p_h, NN);
    k_agg<<<2048, T>>>(p_h, bc + 2 * DF, p_xhi, p_xlo, p_bnsum + 2 * DF, p_bnsq + 2 * DF);

    // ---- pool ----
    k_pool<<<128, T>>>(p_xhi, p_xlo, bat);

    // ---- head ----
    k_hg0<<<NG, DH>>>(Wh0, bh0, p_bnsum + 2 * DF, p_bnsq + 2 * DF, gc + 2 * DF, bec + 2 * DF);
    k_hg1<<<NG, DH>>>(Wh1, bh1, gh0, beh0);
    k_final<<<NG, DH>>>(Wout, bout, gh1, beh1, out);
}

// round 15
// speedup vs baseline: 1.1182x; 1.1182x over previous
#include <cuda_runtime.h>
#include <cuda_bf16.h>
#include <math.h>
#include <stdint.h>

#define NN 100000
#define NE 1600000
#define DF 128
#define NG 512
#define DH 256
#define SB ((NN + 255) / 256)   // 391 scan blocks

// ------------------- scratch (__device__ globals; no allocation) -------------------
static __device__ int   g_cnt[NN];
static __device__ int   g_wptr[NN];
static __device__ int   g_rowptr[NN + 1];
static __device__ int   g_bsum[512];
static __device__ int   g_boff[512];
static __device__ int   g_col[NE];
static __device__ float g_dinv[NN];
static __device__ __align__(16) float g_x0[(size_t)NN * DF];
static __device__ __align__(16) float g_x1[(size_t)NN * DF];
static __device__ __align__(16) float g_h [(size_t)NN * DF];
static __device__ __align__(16) __nv_bfloat16 g_Whi[DF * DF];  // [n][k]
static __device__ __align__(16) __nv_bfloat16 g_Wlo[DF * DF];  // [n][k]
static __device__ __align__(16) float g_dvec[DF];
static __device__ float g_bnsum[3 * DF];
static __device__ float g_bnsq [3 * DF];
static __device__ __align__(16) float g_pool[NG * DF];
static __device__ float g_gcnt[NG];
static __device__ float g_h0[NG * DH];
static __device__ float g_h1[NG * DH];
static __device__ float g_sq[4 * DH];      // s0,q0,s1,q1

// ------------------- one-shot init -------------------
#define INIT_TOT (NN + 3 * DF * 2 + NG * DF + NG + 4 * DH)
__global__ void k_init() {
    int i = blockIdx.x * blockDim.x + threadIdx.x;
    if (i < NN) { g_cnt[i] = 0; return; }
    i -= NN;
    if (i < 3 * DF) { g_bnsum[i] = 0.f; return; }
    i -= 3 * DF;
    if (i < 3 * DF) { g_bnsq[i] = 0.f; return; }
    i -= 3 * DF;
    if (i < NG * DF) { g_pool[i] = 0.f; return; }
    i -= NG * DF;
    if (i < NG) { g_gcnt[i] = 0.f; return; }
    i -= NG;
    if (i < 4 * DH) g_sq[i] = 0.f;
}

// ------------------- CSR build -------------------
__global__ void k_hist(const int* __restrict__ dst) {
    int e = blockIdx.x * blockDim.x + threadIdx.x;
    if (e < NE) atomicAdd(&g_cnt[dst[e]], 1);
}
__global__ void __launch_bounds__(256) k_scanA() {
    __shared__ int s[256];
    int t = threadIdx.x;
    int i = blockIdx.x * 256 + t;
    int v = (i < NN) ? g_cnt[i] : 0;
    if (i < NN) g_dinv[i] = rsqrtf((float)v + 1.0f);
    s[t] = v;
    __syncthreads();
#pragma unroll
    for (int off = 1; off < 256; off <<= 1) {
        int u = (t >= off) ? s[t - off] : 0;
        __syncthreads();
        s[t] += u;
        __syncthreads();
    }
    if (i < NN) g_rowptr[i] = s[t] - v;
    if (t == 255) g_bsum[blockIdx.x] = s[255];
}
__global__ void __launch_bounds__(512) k_scanB() {
    __shared__ int s[512];
    int t = threadIdx.x;
    int v = (t < SB) ? g_bsum[t] : 0;
    s[t] = v;
    __syncthreads();
#pragma unroll
    for (int off = 1; off < 512; off <<= 1) {
        int u = (t >= off) ? s[t - off] : 0;
        __syncthreads();
        s[t] += u;
        __syncthreads();
    }
    g_boff[t] = s[t] - v;
    if (t == 0) g_rowptr[NN] = NE;
}
__global__ void __launch_bounds__(256) k_scanC() {
    int i = blockIdx.x * 256 + threadIdx.x;
    if (i < NN) {
        int r = g_rowptr[i] + g_boff[blockIdx.x];
        g_rowptr[i] = r;
        g_wptr[i]   = r;
    }
}
__global__ void k_fill(const int* __restrict__ src, const int* __restrict__ dst) {
    int e = blockIdx.x * blockDim.x + threadIdx.x;
    if (e < NE) {
        int v = dst[e];
        int pos = atomicAdd(&g_wptr[v], 1);
        g_col[pos] = src[e];
    }
}

// ------------------- mma.sync helpers -------------------
__device__ __forceinline__ uint32_t smem_u32(const void* p) {
    uint32_t a;
    asm("{ .reg .u64 t; cvta.to.shared.u64 t, %1; cvt.u32.u64 %0, t; }" : "=r"(a) : "l"(p));
    return a;
}
#define LDMX4(r, addr) \
    asm volatile("ldmatrix.sync.aligned.m8n8.x4.shared.b16 {%0,%1,%2,%3}, [%4];" \
        : "=r"((r)[0]), "=r"((r)[1]), "=r"((r)[2]), "=r"((r)[3]) : "r"(addr))
#define MMA_BF16(c, a, b0, b1) \
    asm volatile("mma.sync.aligned.m16n8k16.row.col.f32.bf16.bf16.f32 " \
        "{%0,%1,%2,%3}, {%4,%5,%6,%7}, {%8,%9}, {%0,%1,%2,%3};" \
        : "+f"((c)[0]), "+f"((c)[1]), "+f"((c)[2]), "+f"((c)[3]) \
        : "r"((a)[0]), "r"((a)[1]), "r"((a)[2]), "r"((a)[3]), "r"(b0), "r"(b1))

__device__ __forceinline__ void split8(const float* f, uint4& hi, uint4& lo) {
    uint32_t h[4], l[4];
#pragma unroll
    for (int p = 0; p < 4; p++) {
        __nv_bfloat16 h0 = __float2bfloat16(f[2 * p]);
        __nv_bfloat16 h1 = __float2bfloat16(f[2 * p + 1]);
        __nv_bfloat16 l0 = __float2bfloat16(f[2 * p]     - __bfloat162float(h0));
        __nv_bfloat16 l1 = __float2bfloat16(f[2 * p + 1] - __bfloat162float(h1));
        h[p] = (uint32_t)__bfloat16_as_ushort(h0) | ((uint32_t)__bfloat16_as_ushort(h1) << 16);
        l[p] = (uint32_t)__bfloat16_as_ushort(l0) | ((uint32_t)__bfloat16_as_ushort(l1) << 16);
    }
    hi = make_uint4(h[0], h[1], h[2], h[3]);
    lo = make_uint4(l[0], l[1], l[2], l[3]);
}

// ------------------- persistent tensor-core GEMM: C[M,128] = A @ W + dvec -----------
// Tile M=64 x N=128 x K=128; SMEM 96KB -> 2 CTAs/SM; grid = 296 persistent CTAs.
// B staged ONCE per CTA, then loop over M tiles.
#define SMO_AHI 0
#define SMO_ALO 16384
#define SMO_BHI 32768
#define SMO_BLO 65536
#define SM_TOT  98304
#define GEMM_GRID 296

__global__ void __launch_bounds__(256) k_mmagemm(
    const float* __restrict__ A,
    const __nv_bfloat16* __restrict__ Bhi, const __nv_bfloat16* __restrict__ Blo,
    const float* __restrict__ dvec, float* __restrict__ C, int M)
{
    extern __shared__ char sm[];
    uint32_t sbase = smem_u32(sm);
    int tid = threadIdx.x, lane = tid & 31, wid = tid >> 5;
    int warpM = wid & 1, warpN = wid >> 1;   // 2 x 4

    // stage B once (bf16 [n][k]) with XOR swizzle
    for (int i = tid; i < 2048; i += 256) {
        int n = i >> 4, c = i & 15;
        uint32_t off = n * 256 + (uint32_t)((c ^ (n & 7)) << 4);
        *(uint4*)(sm + SMO_BHI + off) = *(const uint4*)(Bhi + n * 128 + c * 8);
        *(uint4*)(sm + SMO_BLO + off) = *(const uint4*)(Blo + n * 128 + c * 8);
    }

    int a_mrow0 = warpM * 32 + (lane & 15);
    int a_kadd  = (lane >> 4) << 3;
    int b_nadd  = (lane & 7) + ((lane >> 4) << 3);
    int b_kadd  = ((lane >> 3) & 1) << 3;

    int nTiles = (M + 63) / 64;
    for (int tile = blockIdx.x; tile < nTiles; tile += gridDim.x) {
        int row0 = tile * 64;
        __syncthreads();   // prior epilogue done (and, 1st iter, covers B staging ordering)

        // stage + split A (64 rows)
        for (int i = tid; i < 1024; i += 256) {
            int m = i >> 4, c = i & 15;
            int row = row0 + m;
            float f[8];
            if (row < M) {
                float4 f0 = *(const float4*)(A + (size_t)row * 128 + c * 8);
                float4 f1 = *(const float4*)(A + (size_t)row * 128 + c * 8 + 4);
                f[0] = f0.x; f[1] = f0.y; f[2] = f0.z; f[3] = f0.w;
                f[4] = f1.x; f[5] = f1.y; f[6] = f1.z; f[7] = f1.w;
            } else {
#pragma unroll
                for (int p = 0; p < 8; p++) f[p] = 0.f;
            }
            uint4 hi, lo;
            split8(f, hi, lo);
            uint32_t off = m * 256 + (uint32_t)((c ^ (m & 7)) << 4);
            *(uint4*)(sm + SMO_AHI + off) = hi;
            *(uint4*)(sm + SMO_ALO + off) = lo;
        }
        __syncthreads();

        float acc[2][4][4];
#pragma unroll
        for (int i = 0; i < 2; i++)
#pragma unroll
            for (int j = 0; j < 4; j++)
#pragma unroll
                for (int q = 0; q < 4; q++) acc[i][j][q] = 0.f;

#pragma unroll
        for (int ks = 0; ks < 8; ks++) {
            int K0 = ks * 16;
            uint32_t ahi[2][4], alo[2][4];
#pragma unroll
            for (int fm = 0; fm < 2; fm++) {
                int mrow = a_mrow0 + fm * 16;
                int kk = K0 + a_kadd;
                uint32_t off = mrow * 256 + (uint32_t)((((kk >> 3) ^ (mrow & 7)) << 4));
                LDMX4(ahi[fm], sbase + SMO_AHI + off);
                LDMX4(alo[fm], sbase + SMO_ALO + off);
            }
#pragma unroll
            for (int nb = 0; nb < 2; nb++) {
                int nrow = warpN * 32 + nb * 16 + b_nadd;
                int kk = K0 + b_kadd;
                uint32_t off = nrow * 256 + (uint32_t)((((kk >> 3) ^ (nrow & 7)) << 4));
                uint32_t bhi[4], blo[4];
                LDMX4(bhi, sbase + SMO_BHI + off);
                LDMX4(blo, sbase + SMO_BLO + off);
#pragma unroll
                for (int fm = 0; fm < 2; fm++) {
                    MMA_BF16(acc[fm][nb * 2 + 0], ahi[fm], bhi[0], bhi[1]);
                    MMA_BF16(acc[fm][nb * 2 + 1], ahi[fm], bhi[2], bhi[3]);
                }
#pragma unroll
                for (int fm = 0; fm < 2; fm++) {
                    MMA_BF16(acc[fm][nb * 2 + 0], ahi[fm], blo[0], blo[1]);
                    MMA_BF16(acc[fm][nb * 2 + 1], ahi[fm], blo[2], blo[3]);
                }
#pragma unroll
                for (int fm = 0; fm < 2; fm++) {
                    MMA_BF16(acc[fm][nb * 2 + 0], alo[fm], bhi[0], bhi[1]);
                    MMA_BF16(acc[fm][nb * 2 + 1], alo[fm], bhi[2], bhi[3]);
                }
            }
        }

        // epilogue (no smem use)
#pragma unroll
        for (int fm = 0; fm < 2; fm++) {
#pragma unroll
            for (int nf = 0; nf < 4; nf++) {
                int r = row0 + warpM * 32 + fm * 16 + (lane >> 2);
                int col = warpN * 32 + nf * 8 + (lane & 3) * 2;
                float d0 = dvec ? dvec[col] : 0.f;
                float d1 = dvec ? dvec[col + 1] : 0.f;
                if (r < M)
                    *(float2*)(C + (size_t)r * 128 + col) =
                        make_float2(acc[fm][nf][0] + d0, acc[fm][nf][1] + d1);
                if (r + 8 < M)
                    *(float2*)(C + (size_t)(r + 8) * 128 + col) =
                        make_float2(acc[fm][nf][2] + d0, acc[fm][nf][3] + d1);
            }
        }
    }
}

// ------------------- W prep with in-block BN affine (bnsum==null -> identity) -------
__global__ void k_wprep(const float* __restrict__ W,
                        const float* __restrict__ bnsum, const float* __restrict__ bnsq,
                        const float* __restrict__ gamma, const float* __restrict__ beta) {
    const float invN = 1.0f / NN;
    if (blockIdx.x < 64) {
        int i = blockIdx.x * 256 + threadIdx.x;   // 0..16383
        int n = i >> 7, k = i & 127;
        float a = 1.0f;
        if (bnsum) {
            float m   = bnsum[k] * invN;
            float var = bnsq[k] * invN - m * m;
            a = gamma[k] * rsqrtf(var + 1e-5f);
        }
        float w = a * W[k * DF + n];
        __nv_bfloat16 hi = __float2bfloat16(w);
        __nv_bfloat16 lo = __float2bfloat16(w - __bfloat162float(hi));
        g_Whi[n * DF + k] = hi;
        g_Wlo[n * DF + k] = lo;
    } else if (bnsum) {
        __shared__ float sc[DF];
        int j = threadIdx.x;
        if (j < DF) {
            float m   = bnsum[j] * invN;
            float var = bnsq[j] * invN - m * m;
            float a   = gamma[j] * rsqrtf(var + 1e-5f);
            sc[j] = beta[j] - a * m;
        }
        __syncthreads();
        if (j < DF) {
            float s = 0.f;
#pragma unroll 8
            for (int k = 0; k < DF; k++) s = fmaf(sc[k], W[k * DF + j], s);
            g_dvec[j] = s;
        }
    }
}

// ------------------- GCN aggregation + bias + relu + fused BN stats -----------------
__global__ void __launch_bounds__(256) k_agg(
    const float* __restrict__ h, const float* __restrict__ bias,
    float* __restrict__ xout, float* __restrict__ bnsum, float* __restrict__ bnsq)
{
    __shared__ float bs[DF], bq[DF];
    int tid = threadIdx.x;
    if (tid < DF) { bs[tid] = 0.f; bq[tid] = 0.f; }
    __syncthreads();

    int lane = tid & 31;
    int w    = tid >> 5;
    int warpId = blockIdx.x * (blockDim.x >> 5) + w;
    int nW     = gridDim.x * (blockDim.x >> 5);

    float4 bv = *(const float4*)(bias + lane * 4);
    float ls0 = 0, ls1 = 0, ls2 = 0, ls3 = 0;
    float lq0 = 0, lq1 = 0, lq2 = 0, lq3 = 0;

    for (int v = warpId; v < NN; v += nW) {
        float dv = g_dinv[v];
        float4 hv = *((const float4*)(h + (size_t)v * DF) + lane);
        float ax = hv.x * dv, ay = hv.y * dv, az = hv.z * dv, aw = hv.w * dv;

        int beg = g_rowptr[v], end = g_rowptr[v + 1];
        for (int e0 = beg; e0 < end; e0 += 32) {
            int idx = e0 + lane;
            int   sl = (idx < end) ? g_col[idx]  : 0;
            float dl = (idx < end) ? g_dinv[sl]  : 0.f;
            int m = end - e0; if (m > 32) m = 32;
            for (int j = 0; j < m; j++) {
                int   sj  = __shfl_sync(0xffffffffu, sl, j);
                float dsj = __shfl_sync(0xffffffffu, dl, j);
                float4 hs = *((const float4*)(h + (size_t)sj * DF) + lane);
                ax = fmaf(hs.x, dsj, ax);
                ay = fmaf(hs.y, dsj, ay);
                az = fmaf(hs.z, dsj, az);
                aw = fmaf(hs.w, dsj, aw);
            }
        }
        float ox = fmaxf(fmaf(ax, dv, bv.x), 0.f);
        float oy = fmaxf(fmaf(ay, dv, bv.y), 0.f);
        float oz = fmaxf(fmaf(az, dv, bv.z), 0.f);
        float ow = fmaxf(fmaf(aw, dv, bv.w), 0.f);
        *((float4*)(xout + (size_t)v * DF) + lane) = make_float4(ox, oy, oz, ow);
        ls0 += ox; lq0 += ox * ox;
        ls1 += oy; lq1 += oy * oy;
        ls2 += oz; lq2 += oz * oz;
        ls3 += ow; lq3 += ow * ow;
    }
    atomicAdd(&bs[lane * 4 + 0], ls0); atomicAdd(&bq[lane * 4 + 0], lq0);
    atomicAdd(&bs[lane * 4 + 1], ls1); atomicAdd(&bq[lane * 4 + 1], lq1);
    atomicAdd(&bs[lane * 4 + 2], ls2); atomicAdd(&bq[lane * 4 + 2], lq2);
    atomicAdd(&bs[lane * 4 + 3], ls3); atomicAdd(&bq[lane * 4 + 3], lq3);
    __syncthreads();
    if (tid < DF) {
        atomicAdd(&bnsum[tid], bs[tid]);
        atomicAdd(&bnsq[tid],  bq[tid]);
    }
}

// ------------------- global_add_pool -------------------
__global__ void k_pool(const float* __restrict__ x, const int* __restrict__ batch) {
    int lane = threadIdx.x & 31;
    int w    = (blockIdx.x * blockDim.x + threadIdx.x) >> 5;
    int nW   = (gridDim.x * blockDim.x) >> 5;
    int C    = (NN + nW - 1) / nW;
    int beg = w * C;
    int end = beg + C; if (end > NN) end = NN;
    if (beg >= end) return;

    float a0 = 0, a1 = 0, a2 = 0, a3 = 0, cntf = 0;
    int cur = batch[beg];
    for (int v = beg; v < end; v++) {
        int g = batch[v];
        if (g != cur) {
            atomicAdd(&g_pool[cur * DF + lane * 4 + 0], a0);
            atomicAdd(&g_pool[cur * DF + lane * 4 + 1], a1);
            atomicAdd(&g_pool[cur * DF + lane * 4 + 2], a2);
            atomicAdd(&g_pool[cur * DF + lane * 4 + 3], a3);
            if (lane == 0) atomicAdd(&g_gcnt[cur], cntf);
            a0 = a1 = a2 = a3 = 0.f; cntf = 0.f; cur = g;
        }
        float4 xv = *((const float4*)(x + (size_t)v * DF) + lane);
        a0 += xv.x; a1 += xv.y; a2 += xv.z; a3 += xv.w; cntf += 1.f;
    }
    atomicAdd(&g_pool[cur * DF + lane * 4 + 0], a0);
    atomicAdd(&g_pool[cur * DF + lane * 4 + 1], a1);
    atomicAdd(&g_pool[cur * DF + lane * 4 + 2], a2);
    atomicAdd(&g_pool[cur * DF + lane * 4 + 3], a3);
    if (lane == 0) atomicAdd(&g_gcnt[cur], cntf);
}

// ------------------- head (BN affine computed in-block) -------------------
__global__ void __launch_bounds__(256) k_hg0(
    const float* __restrict__ Wh0, const float* __restrict__ bh0,
    const float* __restrict__ bnsum, const float* __restrict__ bnsq,
    const float* __restrict__ gamma, const float* __restrict__ beta) {
    __shared__ float sx[DF];
    int g = blockIdx.x, j = threadIdx.x;
    if (j < DF) {
        const float invN = 1.0f / NN;
        float m   = bnsum[j] * invN;
        float var = bnsq[j] * invN - m * m;
        float a   = gamma[j] * rsqrtf(var + 1e-5f);
        float c   = beta[j] - a * m;
        sx[j] = a * g_pool[g * DF + j] + c * g_gcnt[g];
    }
    __syncthreads();
    float acc = bh0[j];
#pragma unroll 8
    for (int k = 0; k < DF; k++) acc = fmaf(sx[k], Wh0[k * DH + j], acc);
    float v = fmaxf(acc, 0.f);
    g_h0[g * DH + j] = v;
    atomicAdd(&g_sq[j], v);
    atomicAdd(&g_sq[DH + j], v * v);
}
__global__ void __launch_bounds__(256) k_hg1(
    const float* __restrict__ Wh1, const float* __restrict__ bh1,
    const float* __restrict__ gamma, const float* __restrict__ beta) {
    __shared__ float sx[DH];
    int g = blockIdx.x, j = threadIdx.x;
    {
        const float invG = 1.0f / NG;
        float m   = g_sq[j] * invG;
        float var = g_sq[DH + j] * invG - m * m;
        float a   = gamma[j] * rsqrtf(var + 1e-5f);
        float c   = beta[j] - a * m;
        sx[j] = a * g_h0[g * DH + j] + c;
    }
    __syncthreads();
    float acc = bh1[j];
#pragma unroll 8
    for (int k = 0; k < DH; k++) acc = fmaf(sx[k], Wh1[k * DH + j], acc);
    float v = fmaxf(acc, 0.f);
    g_h1[g * DH + j] = v;
    atomicAdd(&g_sq[2 * DH + j], v);
    atomicAdd(&g_sq[3 * DH + j], v * v);
}
__global__ void __launch_bounds__(256) k_final(
    const float* __restrict__ Wout, const float* __restrict__ bout,
    const float* __restrict__ gamma, const float* __restrict__ beta,
    float* __restrict__ out) {
    __shared__ float red[DH];
    int g = blockIdx.x, t = threadIdx.x;
    {
        const float invG = 1.0f / NG;
        float m   = g_sq[2 * DH + t] * invG;
        float var = g_sq[3 * DH + t] * invG - m * m;
        float a   = gamma[t] * rsqrtf(var + 1e-5f);
        float c   = beta[t] - a * m;
        red[t] = (a * g_h1[g * DH + t] + c) * Wout[t];
    }
    __syncthreads();
    for (int o = DH / 2; o > 0; o >>= 1) {
        if (t < o) red[t] += red[t + o];
        __syncthreads();
    }
    if (t == 0) out[g] = red[0] + bout[0];
}

// ------------------- launch -------------------
extern "C" void kernel_launch(void* const* d_in, const int* in_sizes, int n_in,
                              void* d_out, int out_size) {
    const float* x   = (const float*)d_in[0];
    const int*   ei  = (const int*)d_in[1];
    const int*   bat = (const int*)d_in[2];
    const float* Wc  = (const float*)d_in[3];
    const float* bc  = (const float*)d_in[4];
    const float* gc  = (const float*)d_in[5];
    const float* bec = (const float*)d_in[6];
    const float* Wh0 = (const float*)d_in[7];
    const float* bh0 = (const float*)d_in[8];
    const float* gh0 = (const float*)d_in[9];
    const float* beh0= (const float*)d_in[10];
    const float* Wh1 = (const float*)d_in[11];
    const float* bh1 = (const float*)d_in[12];
    const float* gh1 = (const float*)d_in[13];
    const float* beh1= (const float*)d_in[14];
    const float* Wout= (const float*)d_in[15];
    const float* bout= (const float*)d_in[16];
    float* out = (float*)d_out;

    const int* src = ei;
    const int* dst = ei + NE;

    float *p_x0, *p_x1, *p_h, *p_dvec, *p_bnsum, *p_bnsq;
    __nv_bfloat16 *p_Whi, *p_Wlo;
    cudaGetSymbolAddress((void**)&p_x0,   g_x0);
    cudaGetSymbolAddress((void**)&p_x1,   g_x1);
    cudaGetSymbolAddress((void**)&p_h,    g_h);
    cudaGetSymbolAddress((void**)&p_Whi,  g_Whi);
    cudaGetSymbolAddress((void**)&p_Wlo,  g_Wlo);
    cudaGetSymbolAddress((void**)&p_dvec, g_dvec);
    cudaGetSymbolAddress((void**)&p_bnsum,g_bnsum);
    cudaGetSymbolAddress((void**)&p_bnsq, g_bnsq);

    cudaFuncSetAttribute(k_mmagemm, cudaFuncAttributeMaxDynamicSharedMemorySize, SM_TOT);

    static cudaStream_t s_side = nullptr;
    static cudaEvent_t  e_fork = nullptr, e_join = nullptr;
    if (!s_side) {
        cudaStreamCreateWithFlags(&s_side, cudaStreamNonBlocking);
        cudaEventCreateWithFlags(&e_fork, cudaEventDisableTiming);
        cudaEventCreateWithFlags(&e_join, cudaEventDisableTiming);
    }

    const int T = 256;

    // ---- init (main stream), then fork CSR build onto side stream ----
    k_init<<<(INIT_TOT + T - 1) / T, T>>>();
    cudaEventRecord(e_fork, 0);
    cudaStreamWaitEvent(s_side, e_fork, 0);
    k_hist <<<(NE + T - 1) / T, T, 0, s_side>>>(dst);
    k_scanA<<<SB, 256, 0, s_side>>>();
    k_scanB<<<1, 512, 0, s_side>>>();
    k_scanC<<<SB, 256, 0, s_side>>>();
    k_fill <<<(NE + T - 1) / T, T, 0, s_side>>>(src, dst);
    cudaEventRecord(e_join, s_side);

    // ---- main stream: layer-0 wprep + GEMM overlap CSR build ----
    k_wprep<<<65, T>>>(Wc, nullptr, nullptr, nullptr, nullptr);
    k_mmagemm<<<GEMM_GRID, T, SM_TOT>>>(x, p_Whi, p_Wlo, nullptr, p_h, NN);
    cudaStreamWaitEvent(0, e_join, 0);
    k_agg<<<2048, T>>>(p_h, bc, p_x0, p_bnsum, p_bnsq);

    // ---- conv layer 1 ----
    k_wprep<<<65, T>>>(Wc + DF * DF, p_bnsum, p_bnsq, gc, bec);
    k_mmagemm<<<GEMM_GRID, T, SM_TOT>>>(p_x0, p_Whi, p_Wlo, p_dvec, p_h, NN);
    k_agg<<<2048, T>>>(p_h, bc + DF, p_x1, p_bnsum + DF, p_bnsq + DF);

    // ---- conv layer 2 ----
    k_wprep<<<65, T>>>(Wc + 2 * DF * DF, p_bnsum + DF, p_bnsq + DF, gc + DF, bec + DF);
    k_mmagemm<<<GEMM_GRID, T, SM_TOT>>>(p_x1, p_Whi, p_Wlo, p_dvec, p_h, NN);
    k_agg<<<2048, T>>>(p_h, bc + 2 * DF, p_x0, p_bnsum + 2 * DF, p_bnsq + 2 * DF);

    // ---- pool ----
    k_pool<<<128, T>>>(p_x0, bat);

    // ---- head ----
    k_hg0<<<NG, DH>>>(Wh0, bh0, p_bnsum + 2 * DF, p_bnsq + 2 * DF, gc + 2 * DF, bec + 2 * DF);
    k_hg1<<<NG, DH>>>(Wh1, bh1, gh0, beh0);
    k_final<<<NG, DH>>>(Wout, bout, gh1, beh1, out);
}

// round 16
// speedup vs baseline: 1.1571x; 1.0348x over previous
#include <cuda_runtime.h>
#include <cuda_bf16.h>
#include <math.h>
#include <stdint.h>

#define NN 100000
#define NE 1600000
#define DF 128
#define NG 512
#define DH 256
#define SB ((NN + 255) / 256)   // 391 scan blocks

// ------------------- scratch (__device__ globals; no allocation) -------------------
static __device__ int   g_cnt[NN];
static __device__ int   g_wptr[NN];
static __device__ int   g_rowptr[NN + 1];
static __device__ int   g_bsum[512];
static __device__ int   g_boff[512];
static __device__ int   g_col[NE];
static __device__ float g_dinv[NN];
static __device__ __align__(16) float g_x0[(size_t)NN * DF];
static __device__ __align__(16) float g_x1[(size_t)NN * DF];
static __device__ __align__(16) float g_h [(size_t)NN * DF];
static __device__ __align__(16) __nv_bfloat16 g_Whi[DF * DF];  // [n][k]
static __device__ __align__(16) __nv_bfloat16 g_Wlo[DF * DF];  // [n][k]
static __device__ __align__(16) float g_dvec[DF];
static __device__ float g_bnsum[3 * DF];
static __device__ float g_bnsq [3 * DF];
static __device__ __align__(16) float g_pool[NG * DF];
static __device__ float g_gcnt[NG];
static __device__ float g_h0[NG * DH];
static __device__ float g_h1[NG * DH];
static __device__ float g_sq[4 * DH];      // s0,q0,s1,q1

// ------------------- one-shot init -------------------
#define INIT_TOT (NN + 3 * DF * 2 + NG * DF + NG + 4 * DH)
__global__ void k_init() {
    int i = blockIdx.x * blockDim.x + threadIdx.x;
    if (i < NN) { g_cnt[i] = 0; return; }
    i -= NN;
    if (i < 3 * DF) { g_bnsum[i] = 0.f; return; }
    i -= 3 * DF;
    if (i < 3 * DF) { g_bnsq[i] = 0.f; return; }
    i -= 3 * DF;
    if (i < NG * DF) { g_pool[i] = 0.f; return; }
    i -= NG * DF;
    if (i < NG) { g_gcnt[i] = 0.f; return; }
    i -= NG;
    if (i < 4 * DH) g_sq[i] = 0.f;
}

// ------------------- CSR build -------------------
__global__ void k_hist(const int* __restrict__ dst) {
    int e = blockIdx.x * blockDim.x + threadIdx.x;
    if (e < NE) atomicAdd(&g_cnt[dst[e]], 1);
}
__global__ void __launch_bounds__(256) k_scanA() {
    __shared__ int s[256];
    int t = threadIdx.x;
    int i = blockIdx.x * 256 + t;
    int v = (i < NN) ? g_cnt[i] : 0;
    if (i < NN) g_dinv[i] = rsqrtf((float)v + 1.0f);
    s[t] = v;
    __syncthreads();
#pragma unroll
    for (int off = 1; off < 256; off <<= 1) {
        int u = (t >= off) ? s[t - off] : 0;
        __syncthreads();
        s[t] += u;
        __syncthreads();
    }
    if (i < NN) g_rowptr[i] = s[t] - v;
    if (t == 255) g_bsum[blockIdx.x] = s[255];
}
__global__ void __launch_bounds__(512) k_scanB() {
    __shared__ int s[512];
    int t = threadIdx.x;
    int v = (t < SB) ? g_bsum[t] : 0;
    s[t] = v;
    __syncthreads();
#pragma unroll
    for (int off = 1; off < 512; off <<= 1) {
        int u = (t >= off) ? s[t - off] : 0;
        __syncthreads();
        s[t] += u;
        __syncthreads();
    }
    g_boff[t] = s[t] - v;
    if (t == 0) g_rowptr[NN] = NE;
}
__global__ void __launch_bounds__(256) k_scanC() {
    int i = blockIdx.x * 256 + threadIdx.x;
    if (i < NN) {
        int r = g_rowptr[i] + g_boff[blockIdx.x];
        g_rowptr[i] = r;
        g_wptr[i]   = r;
    }
}
__global__ void k_fill(const int* __restrict__ src, const int* __restrict__ dst) {
    int e = blockIdx.x * blockDim.x + threadIdx.x;
    if (e < NE) {
        int v = dst[e];
        int pos = atomicAdd(&g_wptr[v], 1);
        g_col[pos] = src[e];
    }
}

// ------------------- mma.sync helpers -------------------
__device__ __forceinline__ uint32_t smem_u32(const void* p) {
    uint32_t a;
    asm("{ .reg .u64 t; cvta.to.shared.u64 t, %1; cvt.u32.u64 %0, t; }" : "=r"(a) : "l"(p));
    return a;
}
#define LDMX4(r, addr) \
    asm volatile("ldmatrix.sync.aligned.m8n8.x4.shared.b16 {%0,%1,%2,%3}, [%4];" \
        : "=r"((r)[0]), "=r"((r)[1]), "=r"((r)[2]), "=r"((r)[3]) : "r"(addr))
#define MMA_BF16(c, a, b0, b1) \
    asm volatile("mma.sync.aligned.m16n8k16.row.col.f32.bf16.bf16.f32 " \
        "{%0,%1,%2,%3}, {%4,%5,%6,%7}, {%8,%9}, {%0,%1,%2,%3};" \
        : "+f"((c)[0]), "+f"((c)[1]), "+f"((c)[2]), "+f"((c)[3]) \
        : "r"((a)[0]), "r"((a)[1]), "r"((a)[2]), "r"((a)[3]), "r"(b0), "r"(b1))

// ------------------- persistent tensor-core GEMM with A register prefetch -----------
// Tile M=64 x N=128 x K=128; SMEM 96KB -> 2 CTAs/SM; grid = 296 persistent CTAs.
#define SMO_AHI 0
#define SMO_ALO 16384
#define SMO_BHI 32768
#define SMO_BLO 65536
#define SM_TOT  98304
#define GEMM_GRID 296

__global__ void __launch_bounds__(256) k_mmagemm(
    const float* __restrict__ A,
    const __nv_bfloat16* __restrict__ Bhi, const __nv_bfloat16* __restrict__ Blo,
    const float* __restrict__ dvec, float* __restrict__ C, int M)
{
    extern __shared__ char sm[];
    uint32_t sbase = smem_u32(sm);
    int tid = threadIdx.x, lane = tid & 31, wid = tid >> 5;
    int warpM = wid & 1, warpN = wid >> 1;   // 2 x 4

    // stage B once (bf16 [n][k]) with XOR swizzle
    for (int i = tid; i < 2048; i += 256) {
        int n = i >> 4, c = i & 15;
        uint32_t off = n * 256 + (uint32_t)((c ^ (n & 7)) << 4);
        *(uint4*)(sm + SMO_BHI + off) = *(const uint4*)(Bhi + n * 128 + c * 8);
        *(uint4*)(sm + SMO_BLO + off) = *(const uint4*)(Blo + n * 128 + c * 8);
    }

    int a_mrow0 = warpM * 32 + (lane & 15);
    int a_kadd  = (lane >> 4) << 3;
    int b_nadd  = (lane & 7) + ((lane >> 4) << 3);
    int b_kadd  = ((lane >> 3) & 1) << 3;

    // this thread's 4 staging slots: i = tid + s*256; m = i>>4, c = i&15
    int sm_m[4], sm_c[4];
#pragma unroll
    for (int s = 0; s < 4; s++) {
        int i = tid + s * 256;
        sm_m[s] = i >> 4;
        sm_c[s] = i & 15;
    }

    int nTiles = (M + 63) / 64;
    int tile = blockIdx.x;
    if (tile >= nTiles) return;

    // prefetch first tile's A into registers
    float4 pf[4][2];
#pragma unroll
    for (int s = 0; s < 4; s++) {
        int row = tile * 64 + sm_m[s];
        if (row < M) {
            pf[s][0] = *(const float4*)(A + (size_t)row * 128 + sm_c[s] * 8);
            pf[s][1] = *(const float4*)(A + (size_t)row * 128 + sm_c[s] * 8 + 4);
        } else {
            pf[s][0] = make_float4(0.f, 0.f, 0.f, 0.f);
            pf[s][1] = pf[s][0];
        }
    }

    for (; tile < nTiles; tile += gridDim.x) {
        int row0 = tile * 64;
        __syncthreads();   // prior epilogue done / B staged

        // split prefetched A regs -> smem
#pragma unroll
        for (int s = 0; s < 4; s++) {
            float f[8] = {pf[s][0].x, pf[s][0].y, pf[s][0].z, pf[s][0].w,
                          pf[s][1].x, pf[s][1].y, pf[s][1].z, pf[s][1].w};
            uint32_t hw[4], lw[4];
#pragma unroll
            for (int p = 0; p < 4; p++) {
                __nv_bfloat16 h0 = __float2bfloat16(f[2 * p]);
                __nv_bfloat16 h1 = __float2bfloat16(f[2 * p + 1]);
                __nv_bfloat16 l0 = __float2bfloat16(f[2 * p]     - __bfloat162float(h0));
                __nv_bfloat16 l1 = __float2bfloat16(f[2 * p + 1] - __bfloat162float(h1));
                hw[p] = (uint32_t)__bfloat16_as_ushort(h0) | ((uint32_t)__bfloat16_as_ushort(h1) << 16);
                lw[p] = (uint32_t)__bfloat16_as_ushort(l0) | ((uint32_t)__bfloat16_as_ushort(l1) << 16);
            }
            uint32_t off = sm_m[s] * 256 + (uint32_t)((sm_c[s] ^ (sm_m[s] & 7)) << 4);
            *(uint4*)(sm + SMO_AHI + off) = make_uint4(hw[0], hw[1], hw[2], hw[3]);
            *(uint4*)(sm + SMO_ALO + off) = make_uint4(lw[0], lw[1], lw[2], lw[3]);
        }
        __syncthreads();

        // prefetch NEXT tile's A (loads complete during MMA phase)
        int ntile = tile + gridDim.x;
        if (ntile < nTiles) {
#pragma unroll
            for (int s = 0; s < 4; s++) {
                int row = ntile * 64 + sm_m[s];
                if (row < M) {
                    pf[s][0] = *(const float4*)(A + (size_t)row * 128 + sm_c[s] * 8);
                    pf[s][1] = *(const float4*)(A + (size_t)row * 128 + sm_c[s] * 8 + 4);
                } else {
                    pf[s][0] = make_float4(0.f, 0.f, 0.f, 0.f);
                    pf[s][1] = pf[s][0];
                }
            }
        }

        float acc[2][4][4];
#pragma unroll
        for (int i = 0; i < 2; i++)
#pragma unroll
            for (int j = 0; j < 4; j++)
#pragma unroll
                for (int q = 0; q < 4; q++) acc[i][j][q] = 0.f;

#pragma unroll
        for (int ks = 0; ks < 8; ks++) {
            int K0 = ks * 16;
            uint32_t ahi[2][4], alo[2][4];
#pragma unroll
            for (int fm = 0; fm < 2; fm++) {
                int mrow = a_mrow0 + fm * 16;
                int kk = K0 + a_kadd;
                uint32_t off = mrow * 256 + (uint32_t)((((kk >> 3) ^ (mrow & 7)) << 4));
                LDMX4(ahi[fm], sbase + SMO_AHI + off);
                LDMX4(alo[fm], sbase + SMO_ALO + off);
            }
#pragma unroll
            for (int nb = 0; nb < 2; nb++) {
                int nrow = warpN * 32 + nb * 16 + b_nadd;
                int kk = K0 + b_kadd;
                uint32_t off = nrow * 256 + (uint32_t)((((kk >> 3) ^ (nrow & 7)) << 4));
                uint32_t bhi[4], blo[4];
                LDMX4(bhi, sbase + SMO_BHI + off);
                LDMX4(blo, sbase + SMO_BLO + off);
#pragma unroll
                for (int fm = 0; fm < 2; fm++) {
                    MMA_BF16(acc[fm][nb * 2 + 0], ahi[fm], bhi[0], bhi[1]);
                    MMA_BF16(acc[fm][nb * 2 + 1], ahi[fm], bhi[2], bhi[3]);
                }
#pragma unroll
                for (int fm = 0; fm < 2; fm++) {
                    MMA_BF16(acc[fm][nb * 2 + 0], ahi[fm], blo[0], blo[1]);
                    MMA_BF16(acc[fm][nb * 2 + 1], ahi[fm], blo[2], blo[3]);
                }
#pragma unroll
                for (int fm = 0; fm < 2; fm++) {
                    MMA_BF16(acc[fm][nb * 2 + 0], alo[fm], bhi[0], bhi[1]);
                    MMA_BF16(acc[fm][nb * 2 + 1], alo[fm], bhi[2], bhi[3]);
                }
            }
        }

        // epilogue (no smem use)
#pragma unroll
        for (int fm = 0; fm < 2; fm++) {
#pragma unroll
            for (int nf = 0; nf < 4; nf++) {
                int r = row0 + warpM * 32 + fm * 16 + (lane >> 2);
                int col = warpN * 32 + nf * 8 + (lane & 3) * 2;
                float d0 = dvec ? dvec[col] : 0.f;
                float d1 = dvec ? dvec[col + 1] : 0.f;
                if (r < M)
                    *(float2*)(C + (size_t)r * 128 + col) =
                        make_float2(acc[fm][nf][0] + d0, acc[fm][nf][1] + d1);
                if (r + 8 < M)
                    *(float2*)(C + (size_t)(r + 8) * 128 + col) =
                        make_float2(acc[fm][nf][2] + d0, acc[fm][nf][3] + d1);
            }
        }
    }
}

// ------------------- W prep with in-block BN affine (bnsum==null -> identity) -------
__global__ void k_wprep(const float* __restrict__ W,
                        const float* __restrict__ bnsum, const float* __restrict__ bnsq,
                        const float* __restrict__ gamma, const float* __restrict__ beta) {
    const float invN = 1.0f / NN;
    if (blockIdx.x < 64) {
        int i = blockIdx.x * 256 + threadIdx.x;   // 0..16383
        int n = i >> 7, k = i & 127;
        float a = 1.0f;
        if (bnsum) {
            float m   = bnsum[k] * invN;
            float var = bnsq[k] * invN - m * m;
            a = gamma[k] * rsqrtf(var + 1e-5f);
        }
        float w = a * W[k * DF + n];
        __nv_bfloat16 hi = __float2bfloat16(w);
        __nv_bfloat16 lo = __float2bfloat16(w - __bfloat162float(hi));
        g_Whi[n * DF + k] = hi;
        g_Wlo[n * DF + k] = lo;
    } else if (bnsum) {
        __shared__ float sc[DF];
        int j = threadIdx.x;
        if (j < DF) {
            float m   = bnsum[j] * invN;
            float var = bnsq[j] * invN - m * m;
            float a   = gamma[j] * rsqrtf(var + 1e-5f);
            sc[j] = beta[j] - a * m;
        }
        __syncthreads();
        if (j < DF) {
            float s = 0.f;
#pragma unroll 8
            for (int k = 0; k < DF; k++) s = fmaf(sc[k], W[k * DF + j], s);
            g_dvec[j] = s;
        }
    }
}

// ------------------- GCN aggregation + bias + relu + fused BN stats -----------------
__global__ void __launch_bounds__(256) k_agg(
    const float* __restrict__ h, const float* __restrict__ bias,
    float* __restrict__ xout, float* __restrict__ bnsum, float* __restrict__ bnsq)
{
    __shared__ float bs[DF], bq[DF];
    int tid = threadIdx.x;
    if (tid < DF) { bs[tid] = 0.f; bq[tid] = 0.f; }
    __syncthreads();

    int lane = tid & 31;
    int w    = tid >> 5;
    int warpId = blockIdx.x * (blockDim.x >> 5) + w;
    int nW     = gridDim.x * (blockDim.x >> 5);

    float4 bv = *(const float4*)(bias + lane * 4);
    float ls0 = 0, ls1 = 0, ls2 = 0, ls3 = 0;
    float lq0 = 0, lq1 = 0, lq2 = 0, lq3 = 0;

    for (int v = warpId; v < NN; v += nW) {
        float dv = g_dinv[v];
        float4 hv = *((const float4*)(h + (size_t)v * DF) + lane);
        float ax = hv.x * dv, ay = hv.y * dv, az = hv.z * dv, aw = hv.w * dv;

        int beg = g_rowptr[v], end = g_rowptr[v + 1];
        for (int e0 = beg; e0 < end; e0 += 32) {
            int idx = e0 + lane;
            int   sl = (idx < end) ? g_col[idx]  : 0;
            float dl = (idx < end) ? g_dinv[sl]  : 0.f;
            int m = end - e0; if (m > 32) m = 32;
            for (int j = 0; j < m; j++) {
                int   sj  = __shfl_sync(0xffffffffu, sl, j);
                float dsj = __shfl_sync(0xffffffffu, dl, j);
                float4 hs = *((const float4*)(h + (size_t)sj * DF) + lane);
                ax = fmaf(hs.x, dsj, ax);
                ay = fmaf(hs.y, dsj, ay);
                az = fmaf(hs.z, dsj, az);
                aw = fmaf(hs.w, dsj, aw);
            }
        }
        float ox = fmaxf(fmaf(ax, dv, bv.x), 0.f);
        float oy = fmaxf(fmaf(ay, dv, bv.y), 0.f);
        float oz = fmaxf(fmaf(az, dv, bv.z), 0.f);
        float ow = fmaxf(fmaf(aw, dv, bv.w), 0.f);
        *((float4*)(xout + (size_t)v * DF) + lane) = make_float4(ox, oy, oz, ow);
        ls0 += ox; lq0 += ox * ox;
        ls1 += oy; lq1 += oy * oy;
        ls2 += oz; lq2 += oz * oz;
        ls3 += ow; lq3 += ow * ow;
    }
    atomicAdd(&bs[lane * 4 + 0], ls0); atomicAdd(&bq[lane * 4 + 0], lq0);
    atomicAdd(&bs[lane * 4 + 1], ls1); atomicAdd(&bq[lane * 4 + 1], lq1);
    atomicAdd(&bs[lane * 4 + 2], ls2); atomicAdd(&bq[lane * 4 + 2], lq2);
    atomicAdd(&bs[lane * 4 + 3], ls3); atomicAdd(&bq[lane * 4 + 3], lq3);
    __syncthreads();
    if (tid < DF) {
        atomicAdd(&bnsum[tid], bs[tid]);
        atomicAdd(&bnsq[tid],  bq[tid]);
    }
}

// ------------------- global_add_pool -------------------
__global__ void k_pool(const float* __restrict__ x, const int* __restrict__ batch) {
    int lane = threadIdx.x & 31;
    int w    = (blockIdx.x * blockDim.x + threadIdx.x) >> 5;
    int nW   = (gridDim.x * blockDim.x) >> 5;
    int C    = (NN + nW - 1) / nW;
    int beg = w * C;
    int end = beg + C; if (end > NN) end = NN;
    if (beg >= end) return;

    float a0 = 0, a1 = 0, a2 = 0, a3 = 0, cntf = 0;
    int cur = batch[beg];
    for (int v = beg; v < end; v++) {
        int g = batch[v];
        if (g != cur) {
            atomicAdd(&g_pool[cur * DF + lane * 4 + 0], a0);
            atomicAdd(&g_pool[cur * DF + lane * 4 + 1], a1);
            atomicAdd(&g_pool[cur * DF + lane * 4 + 2], a2);
            atomicAdd(&g_pool[cur * DF + lane * 4 + 3], a3);
            if (lane == 0) atomicAdd(&g_gcnt[cur], cntf);
            a0 = a1 = a2 = a3 = 0.f; cntf = 0.f; cur = g;
        }
        float4 xv = *((const float4*)(x + (size_t)v * DF) + lane);
        a0 += xv.x; a1 += xv.y; a2 += xv.z; a3 += xv.w; cntf += 1.f;
    }
    atomicAdd(&g_pool[cur * DF + lane * 4 + 0], a0);
    atomicAdd(&g_pool[cur * DF + lane * 4 + 1], a1);
    atomicAdd(&g_pool[cur * DF + lane * 4 + 2], a2);
    atomicAdd(&g_pool[cur * DF + lane * 4 + 3], a3);
    if (lane == 0) atomicAdd(&g_gcnt[cur], cntf);
}

// ------------------- head (BN affine computed in-block) -------------------
__global__ void __launch_bounds__(256) k_hg0(
    const float* __restrict__ Wh0, const float* __restrict__ bh0,
    const float* __restrict__ bnsum, const float* __restrict__ bnsq,
    const float* __restrict__ gamma, const float* __restrict__ beta) {
    __shared__ float sx[DF];
    int g = blockIdx.x, j = threadIdx.x;
    if (j < DF) {
        const float invN = 1.0f / NN;
        float m   = bnsum[j] * invN;
        float var = bnsq[j] * invN - m * m;
        float a   = gamma[j] * rsqrtf(var + 1e-5f);
        float c   = beta[j] - a * m;
        sx[j] = a * g_pool[g * DF + j] + c * g_gcnt[g];
    }
    __syncthreads();
    float acc = bh0[j];
#pragma unroll 8
    for (int k = 0; k < DF; k++) acc = fmaf(sx[k], Wh0[k * DH + j], acc);
    float v = fmaxf(acc, 0.f);
    g_h0[g * DH + j] = v;
    atomicAdd(&g_sq[j], v);
    atomicAdd(&g_sq[DH + j], v * v);
}
__global__ void __launch_bounds__(256) k_hg1(
    const float* __restrict__ Wh1, const float* __restrict__ bh1,
    const float* __restrict__ gamma, const float* __restrict__ beta) {
    __shared__ float sx[DH];
    int g = blockIdx.x, j = threadIdx.x;
    {
        const float invG = 1.0f / NG;
        float m   = g_sq[j] * invG;
        float var = g_sq[DH + j] * invG - m * m;
        float a   = gamma[j] * rsqrtf(var + 1e-5f);
        float c   = beta[j] - a * m;
        sx[j] = a * g_h0[g * DH + j] + c;
    }
    __syncthreads();
    float acc = bh1[j];
#pragma unroll 8
    for (int k = 0; k < DH; k++) acc = fmaf(sx[k], Wh1[k * DH + j], acc);
    float v = fmaxf(acc, 0.f);
    g_h1[g * DH + j] = v;
    atomicAdd(&g_sq[2 * DH + j], v);
    atomicAdd(&g_sq[3 * DH + j], v * v);
}
__global__ void __launch_bounds__(256) k_final(
    const float* __restrict__ Wout, const float* __restrict__ bout,
    const float* __restrict__ gamma, const float* __restrict__ beta,
    float* __restrict__ out) {
    __shared__ float red[DH];
    int g = blockIdx.x, t = threadIdx.x;
    {
        const float invG = 1.0f / NG;
        float m   = g_sq[2 * DH + t] * invG;
        float var = g_sq[3 * DH + t] * invG - m * m;
        float a   = gamma[t] * rsqrtf(var + 1e-5f);
        float c   = beta[t] - a * m;
        red[t] = (a * g_h1[g * DH + t] + c) * Wout[t];
    }
    __syncthreads();
    for (int o = DH / 2; o > 0; o >>= 1) {
        if (t < o) red[t] += red[t + o];
        __syncthreads();
    }
    if (t == 0) out[g] = red[0] + bout[0];
}

// ------------------- launch -------------------
extern "C" void kernel_launch(void* const* d_in, const int* in_sizes, int n_in,
                              void* d_out, int out_size) {
    const float* x   = (const float*)d_in[0];
    const int*   ei  = (const int*)d_in[1];
    const int*   bat = (const int*)d_in[2];
    const float* Wc  = (const float*)d_in[3];
    const float* bc  = (const float*)d_in[4];
    const float* gc  = (const float*)d_in[5];
    const float* bec = (const float*)d_in[6];
    const float* Wh0 = (const float*)d_in[7];
    const float* bh0 = (const float*)d_in[8];
    const float* gh0 = (const float*)d_in[9];
    const float* beh0= (const float*)d_in[10];
    const float* Wh1 = (const float*)d_in[11];
    const float* bh1 = (const float*)d_in[12];
    const float* gh1 = (const float*)d_in[13];
    const float* beh1= (const float*)d_in[14];
    const float* Wout= (const float*)d_in[15];
    const float* bout= (const float*)d_in[16];
    float* out = (float*)d_out;

    const int* src = ei;
    const int* dst = ei + NE;

    float *p_x0, *p_x1, *p_h, *p_dvec, *p_bnsum, *p_bnsq;
    __nv_bfloat16 *p_Whi, *p_Wlo;
    cudaGetSymbolAddress((void**)&p_x0,   g_x0);
    cudaGetSymbolAddress((void**)&p_x1,   g_x1);
    cudaGetSymbolAddress((void**)&p_h,    g_h);
    cudaGetSymbolAddress((void**)&p_Whi,  g_Whi);
    cudaGetSymbolAddress((void**)&p_Wlo,  g_Wlo);
    cudaGetSymbolAddress((void**)&p_dvec, g_dvec);
    cudaGetSymbolAddress((void**)&p_bnsum,g_bnsum);
    cudaGetSymbolAddress((void**)&p_bnsq, g_bnsq);

    cudaFuncSetAttribute(k_mmagemm, cudaFuncAttributeMaxDynamicSharedMemorySize, SM_TOT);

    static cudaStream_t s_side = nullptr;
    static cudaEvent_t  e_fork = nullptr, e_join = nullptr;
    if (!s_side) {
        cudaStreamCreateWithFlags(&s_side, cudaStreamNonBlocking);
        cudaEventCreateWithFlags(&e_fork, cudaEventDisableTiming);
        cudaEventCreateWithFlags(&e_join, cudaEventDisableTiming);
    }

    const int T = 256;

    // ---- init (main stream), then fork CSR build onto side stream ----
    k_init<<<(INIT_TOT + T - 1) / T, T>>>();
    cudaEventRecord(e_fork, 0);
    cudaStreamWaitEvent(s_side, e_fork, 0);
    k_hist <<<(NE + T - 1) / T, T, 0, s_side>>>(dst);
    k_scanA<<<SB, 256, 0, s_side>>>();
    k_scanB<<<1, 512, 0, s_side>>>();
    k_scanC<<<SB, 256, 0, s_side>>>();
    k_fill <<<(NE + T - 1) / T, T, 0, s_side>>>(src, dst);
    cudaEventRecord(e_join, s_side);

    // ---- main stream: layer-0 wprep + GEMM overlap CSR build ----
    k_wprep<<<65, T>>>(Wc, nullptr, nullptr, nullptr, nullptr);
    k_mmagemm<<<GEMM_GRID, T, SM_TOT>>>(x, p_Whi, p_Wlo, nullptr, p_h, NN);
    cudaStreamWaitEvent(0, e_join, 0);
    k_agg<<<2048, T>>>(p_h, bc, p_x0, p_bnsum, p_bnsq);

    // ---- conv layer 1 ----
    k_wprep<<<65, T>>>(Wc + DF * DF, p_bnsum, p_bnsq, gc, bec);
    k_mmagemm<<<GEMM_GRID, T, SM_TOT>>>(p_x0, p_Whi, p_Wlo, p_dvec, p_h, NN);
    k_agg<<<2048, T>>>(p_h, bc + DF, p_x1, p_bnsum + DF, p_bnsq + DF);

    // ---- conv layer 2 ----
    k_wprep<<<65, T>>>(Wc + 2 * DF * DF, p_bnsum + DF, p_bnsq + DF, gc + DF, bec + DF);
    k_mmagemm<<<GEMM_GRID, T, SM_TOT>>>(p_x1, p_Whi, p_Wlo, p_dvec, p_h, NN);
    k_agg<<<2048, T>>>(p_h, bc + 2 * DF, p_x0, p_bnsum + 2 * DF, p_bnsq + 2 * DF);

    // ---- pool ----
    k_pool<<<128, T>>>(p_x0, bat);

    // ---- head ----
    k_hg0<<<NG, DH>>>(Wh0, bh0, p_bnsum + 2 * DF, p_bnsq + 2 * DF, gc + 2 * DF, bec + 2 * DF);
    k_hg1<<<NG, DH>>>(Wh1, bh1, gh0, beh0);
    k_final<<<NG, DH>>>(Wout, bout, gh1, beh1, out);
}

// round 17
// speedup vs baseline: 1.2382x; 1.0700x over previous
#include <cuda_runtime.h>
#include <cuda_bf16.h>
#include <math.h>
#include <stdint.h>

#define NN 100000
#define NE 1600000
#define DF 128
#define NG 512
#define DH 256
#define SB ((NN + 255) / 256)   // 391 scan blocks

// ------------------- scratch (__device__ globals; no allocation) -------------------
static __device__ int   g_cnt[NN];
static __device__ int   g_wptr[NN];
static __device__ int   g_rowptr[NN + 1];
static __device__ int   g_bsum[512];
static __device__ int   g_boff[512];
static __device__ int   g_col[NE];
static __device__ float g_dinv[NN];
static __device__ __align__(16) float g_x[(size_t)NN * DF];   // activations (in-place)
static __device__ __align__(16) float g_h[(size_t)NN * DF];   // conv pre-agg
static __device__ __align__(16) __nv_bfloat16 g_Whi[DF * DF];  // [n][k]
static __device__ __align__(16) __nv_bfloat16 g_Wlo[DF * DF];  // [n][k]
static __device__ __align__(16) float g_dvec[DF];
static __device__ float g_bnsum[3 * DF];
static __device__ float g_bnsq [3 * DF];
static __device__ __align__(16) float g_pool[NG * DF];
static __device__ float g_gcnt[NG];
static __device__ float g_h0[NG * DH];
static __device__ float g_h1[NG * DH];
static __device__ float g_sq[4 * DH];      // s0,q0,s1,q1

// ------------------- one-shot init -------------------
#define INIT_TOT (NN + 3 * DF * 2 + NG * DF + NG + 4 * DH)
__global__ void k_init() {
    int i = blockIdx.x * blockDim.x + threadIdx.x;
    if (i < NN) { g_cnt[i] = 0; return; }
    i -= NN;
    if (i < 3 * DF) { g_bnsum[i] = 0.f; return; }
    i -= 3 * DF;
    if (i < 3 * DF) { g_bnsq[i] = 0.f; return; }
    i -= 3 * DF;
    if (i < NG * DF) { g_pool[i] = 0.f; return; }
    i -= NG * DF;
    if (i < NG) { g_gcnt[i] = 0.f; return; }
    i -= NG;
    if (i < 4 * DH) g_sq[i] = 0.f;
}

// ------------------- CSR build -------------------
__global__ void k_hist(const int* __restrict__ dst) {
    int e = blockIdx.x * blockDim.x + threadIdx.x;
    if (e < NE) atomicAdd(&g_cnt[dst[e]], 1);
}
__global__ void __launch_bounds__(256) k_scanA() {
    __shared__ int s[256];
    int t = threadIdx.x;
    int i = blockIdx.x * 256 + t;
    int v = (i < NN) ? g_cnt[i] : 0;
    if (i < NN) g_dinv[i] = rsqrtf((float)v + 1.0f);
    s[t] = v;
    __syncthreads();
#pragma unroll
    for (int off = 1; off < 256; off <<= 1) {
        int u = (t >= off) ? s[t - off] : 0;
        __syncthreads();
        s[t] += u;
        __syncthreads();
    }
    if (i < NN) g_rowptr[i] = s[t] - v;
    if (t == 255) g_bsum[blockIdx.x] = s[255];
}
__global__ void __launch_bounds__(512) k_scanB() {
    __shared__ int s[512];
    int t = threadIdx.x;
    int v = (t < SB) ? g_bsum[t] : 0;
    s[t] = v;
    __syncthreads();
#pragma unroll
    for (int off = 1; off < 512; off <<= 1) {
        int u = (t >= off) ? s[t - off] : 0;
        __syncthreads();
        s[t] += u;
        __syncthreads();
    }
    g_boff[t] = s[t] - v;
    if (t == 0) g_rowptr[NN] = NE;
}
__global__ void __launch_bounds__(256) k_scanC() {
    int i = blockIdx.x * 256 + threadIdx.x;
    if (i < NN) {
        int r = g_rowptr[i] + g_boff[blockIdx.x];
        g_rowptr[i] = r;
        g_wptr[i]   = r;
    }
}
__global__ void k_fill(const int* __restrict__ src, const int* __restrict__ dst) {
    int e = blockIdx.x * blockDim.x + threadIdx.x;
    if (e < NE) {
        int v = dst[e];
        int pos = atomicAdd(&g_wptr[v], 1);
        g_col[pos] = src[e];
    }
}

// ------------------- mma.sync helpers -------------------
__device__ __forceinline__ uint32_t smem_u32(const void* p) {
    uint32_t a;
    asm("{ .reg .u64 t; cvta.to.shared.u64 t, %1; cvt.u32.u64 %0, t; }" : "=r"(a) : "l"(p));
    return a;
}
#define LDMX4(r, addr) \
    asm volatile("ldmatrix.sync.aligned.m8n8.x4.shared.b16 {%0,%1,%2,%3}, [%4];" \
        : "=r"((r)[0]), "=r"((r)[1]), "=r"((r)[2]), "=r"((r)[3]) : "r"(addr))
#define MMA_BF16(c, a, b0, b1) \
    asm volatile("mma.sync.aligned.m16n8k16.row.col.f32.bf16.bf16.f32 " \
        "{%0,%1,%2,%3}, {%4,%5,%6,%7}, {%8,%9}, {%0,%1,%2,%3};" \
        : "+f"((c)[0]), "+f"((c)[1]), "+f"((c)[2]), "+f"((c)[3]) \
        : "r"((a)[0]), "r"((a)[1]), "r"((a)[2]), "r"((a)[3]), "r"(b0), "r"(b1))

// ------------------- persistent tensor-core GEMM with A register prefetch -----------
// Tile M=64 x N=128 x K=128; SMEM 96KB -> 2 CTAs/SM; grid = 296 persistent CTAs.
#define SMO_AHI 0
#define SMO_ALO 16384
#define SMO_BHI 32768
#define SMO_BLO 65536
#define SM_TOT  98304
#define GEMM_GRID 296

__global__ void __launch_bounds__(256) k_mmagemm(
    const float* __restrict__ A,
    const __nv_bfloat16* __restrict__ Bhi, const __nv_bfloat16* __restrict__ Blo,
    const float* __restrict__ dvec, float* __restrict__ C, int M)
{
    extern __shared__ char sm[];
    uint32_t sbase = smem_u32(sm);
    int tid = threadIdx.x, lane = tid & 31, wid = tid >> 5;
    int warpM = wid & 1, warpN = wid >> 1;   // 2 x 4

    // stage B once (bf16 [n][k]) with XOR swizzle
    for (int i = tid; i < 2048; i += 256) {
        int n = i >> 4, c = i & 15;
        uint32_t off = n * 256 + (uint32_t)((c ^ (n & 7)) << 4);
        *(uint4*)(sm + SMO_BHI + off) = *(const uint4*)(Bhi + n * 128 + c * 8);
        *(uint4*)(sm + SMO_BLO + off) = *(const uint4*)(Blo + n * 128 + c * 8);
    }

    int a_mrow0 = warpM * 32 + (lane & 15);
    int a_kadd  = (lane >> 4) << 3;
    int b_nadd  = (lane & 7) + ((lane >> 4) << 3);
    int b_kadd  = ((lane >> 3) & 1) << 3;

    int sm_m[4], sm_c[4];
#pragma unroll
    for (int s = 0; s < 4; s++) {
        int i = tid + s * 256;
        sm_m[s] = i >> 4;
        sm_c[s] = i & 15;
    }

    int nTiles = (M + 63) / 64;
    int tile = blockIdx.x;
    if (tile >= nTiles) return;

    float4 pf[4][2];
#pragma unroll
    for (int s = 0; s < 4; s++) {
        int row = tile * 64 + sm_m[s];
        if (row < M) {
            pf[s][0] = *(const float4*)(A + (size_t)row * 128 + sm_c[s] * 8);
            pf[s][1] = *(const float4*)(A + (size_t)row * 128 + sm_c[s] * 8 + 4);
        } else {
            pf[s][0] = make_float4(0.f, 0.f, 0.f, 0.f);
            pf[s][1] = pf[s][0];
        }
    }

    for (; tile < nTiles; tile += gridDim.x) {
        int row0 = tile * 64;
        __syncthreads();

        // split prefetched A regs -> smem
#pragma unroll
        for (int s = 0; s < 4; s++) {
            float f[8] = {pf[s][0].x, pf[s][0].y, pf[s][0].z, pf[s][0].w,
                          pf[s][1].x, pf[s][1].y, pf[s][1].z, pf[s][1].w};
            uint32_t hw[4], lw[4];
#pragma unroll
            for (int p = 0; p < 4; p++) {
                __nv_bfloat16 h0 = __float2bfloat16(f[2 * p]);
                __nv_bfloat16 h1 = __float2bfloat16(f[2 * p + 1]);
                __nv_bfloat16 l0 = __float2bfloat16(f[2 * p]     - __bfloat162float(h0));
                __nv_bfloat16 l1 = __float2bfloat16(f[2 * p + 1] - __bfloat162float(h1));
                hw[p] = (uint32_t)__bfloat16_as_ushort(h0) | ((uint32_t)__bfloat16_as_ushort(h1) << 16);
                lw[p] = (uint32_t)__bfloat16_as_ushort(l0) | ((uint32_t)__bfloat16_as_ushort(l1) << 16);
            }
            uint32_t off = sm_m[s] * 256 + (uint32_t)((sm_c[s] ^ (sm_m[s] & 7)) << 4);
            *(uint4*)(sm + SMO_AHI + off) = make_uint4(hw[0], hw[1], hw[2], hw[3]);
            *(uint4*)(sm + SMO_ALO + off) = make_uint4(lw[0], lw[1], lw[2], lw[3]);
        }
        __syncthreads();

        // prefetch NEXT tile's A
        int ntile = tile + gridDim.x;
        if (ntile < nTiles) {
#pragma unroll
            for (int s = 0; s < 4; s++) {
                int row = ntile * 64 + sm_m[s];
                if (row < M) {
                    pf[s][0] = *(const float4*)(A + (size_t)row * 128 + sm_c[s] * 8);
                    pf[s][1] = *(const float4*)(A + (size_t)row * 128 + sm_c[s] * 8 + 4);
                } else {
                    pf[s][0] = make_float4(0.f, 0.f, 0.f, 0.f);
                    pf[s][1] = pf[s][0];
                }
            }
        }

        float acc[2][4][4];
#pragma unroll
        for (int i = 0; i < 2; i++)
#pragma unroll
            for (int j = 0; j < 4; j++)
#pragma unroll
                for (int q = 0; q < 4; q++) acc[i][j][q] = 0.f;

#pragma unroll
        for (int ks = 0; ks < 8; ks++) {
            int K0 = ks * 16;
            uint32_t ahi[2][4], alo[2][4];
#pragma unroll
            for (int fm = 0; fm < 2; fm++) {
                int mrow = a_mrow0 + fm * 16;
                int kk = K0 + a_kadd;
                uint32_t off = mrow * 256 + (uint32_t)((((kk >> 3) ^ (mrow & 7)) << 4));
                LDMX4(ahi[fm], sbase + SMO_AHI + off);
                LDMX4(alo[fm], sbase + SMO_ALO + off);
            }
#pragma unroll
            for (int nb = 0; nb < 2; nb++) {
                int nrow = warpN * 32 + nb * 16 + b_nadd;
                int kk = K0 + b_kadd;
                uint32_t off = nrow * 256 + (uint32_t)((((kk >> 3) ^ (nrow & 7)) << 4));
                uint32_t bhi[4], blo[4];
                LDMX4(bhi, sbase + SMO_BHI + off);
                LDMX4(blo, sbase + SMO_BLO + off);
#pragma unroll
                for (int fm = 0; fm < 2; fm++) {
                    MMA_BF16(acc[fm][nb * 2 + 0], ahi[fm], bhi[0], bhi[1]);
                    MMA_BF16(acc[fm][nb * 2 + 1], ahi[fm], bhi[2], bhi[3]);
                }
#pragma unroll
                for (int fm = 0; fm < 2; fm++) {
                    MMA_BF16(acc[fm][nb * 2 + 0], ahi[fm], blo[0], blo[1]);
                    MMA_BF16(acc[fm][nb * 2 + 1], ahi[fm], blo[2], blo[3]);
                }
#pragma unroll
                for (int fm = 0; fm < 2; fm++) {
                    MMA_BF16(acc[fm][nb * 2 + 0], alo[fm], bhi[0], bhi[1]);
                    MMA_BF16(acc[fm][nb * 2 + 1], alo[fm], bhi[2], bhi[3]);
                }
            }
        }

#pragma unroll
        for (int fm = 0; fm < 2; fm++) {
#pragma unroll
            for (int nf = 0; nf < 4; nf++) {
                int r = row0 + warpM * 32 + fm * 16 + (lane >> 2);
                int col = warpN * 32 + nf * 8 + (lane & 3) * 2;
                float d0 = dvec ? dvec[col] : 0.f;
                float d1 = dvec ? dvec[col + 1] : 0.f;
                if (r < M)
                    *(float2*)(C + (size_t)r * 128 + col) =
                        make_float2(acc[fm][nf][0] + d0, acc[fm][nf][1] + d1);
                if (r + 8 < M)
                    *(float2*)(C + (size_t)(r + 8) * 128 + col) =
                        make_float2(acc[fm][nf][2] + d0, acc[fm][nf][3] + d1);
            }
        }
    }
}

// ------------------- W prep with in-block BN affine (bnsum==null -> identity) -------
__global__ void k_wprep(const float* __restrict__ W,
                        const float* __restrict__ bnsum, const float* __restrict__ bnsq,
                        const float* __restrict__ gamma, const float* __restrict__ beta) {
    const float invN = 1.0f / NN;
    if (blockIdx.x < 64) {
        int i = blockIdx.x * 256 + threadIdx.x;   // 0..16383
        int n = i >> 7, k = i & 127;
        float a = 1.0f;
        if (bnsum) {
            float m   = bnsum[k] * invN;
            float var = bnsq[k] * invN - m * m;
            a = gamma[k] * rsqrtf(var + 1e-5f);
        }
        float w = a * W[k * DF + n];
        __nv_bfloat16 hi = __float2bfloat16(w);
        __nv_bfloat16 lo = __float2bfloat16(w - __bfloat162float(hi));
        g_Whi[n * DF + k] = hi;
        g_Wlo[n * DF + k] = lo;
    } else if (bnsum) {
        __shared__ float sc[DF];
        int j = threadIdx.x;
        if (j < DF) {
            float m   = bnsum[j] * invN;
            float var = bnsq[j] * invN - m * m;
            float a   = gamma[j] * rsqrtf(var + 1e-5f);
            sc[j] = beta[j] - a * m;
        }
        __syncthreads();
        if (j < DF) {
            float s = 0.f;
#pragma unroll 8
            for (int k = 0; k < DF; k++) s = fmaf(sc[k], W[k * DF + j], s);
            g_dvec[j] = s;
        }
    }
}

// ------------------- GCN aggregation + bias + relu + fused BN stats -----------------
__global__ void __launch_bounds__(256) k_agg(
    const float* __restrict__ h, const float* __restrict__ bias,
    float* __restrict__ xout, float* __restrict__ bnsum, float* __restrict__ bnsq)
{
    __shared__ float bs[DF], bq[DF];
    int tid = threadIdx.x;
    if (tid < DF) { bs[tid] = 0.f; bq[tid] = 0.f; }
    __syncthreads();

    int lane = tid & 31;
    int w    = tid >> 5;
    int warpId = blockIdx.x * (blockDim.x >> 5) + w;
    int nW     = gridDim.x * (blockDim.x >> 5);

    float4 bv = *(const float4*)(bias + lane * 4);
    float ls0 = 0, ls1 = 0, ls2 = 0, ls3 = 0;
    float lq0 = 0, lq1 = 0, lq2 = 0, lq3 = 0;

    for (int v = warpId; v < NN; v += nW) {
        float dv = g_dinv[v];
        float4 hv = *((const float4*)(h + (size_t)v * DF) + lane);
        float ax = hv.x * dv, ay = hv.y * dv, az = hv.z * dv, aw = hv.w * dv;

        int beg = g_rowptr[v], end = g_rowptr[v + 1];
        for (int e0 = beg; e0 < end; e0 += 32) {
            int idx = e0 + lane;
            int   sl = (idx < end) ? g_col[idx]  : 0;
            float dl = (idx < end) ? g_dinv[sl]  : 0.f;
            int m = end - e0; if (m > 32) m = 32;
            for (int j = 0; j < m; j++) {
                int   sj  = __shfl_sync(0xffffffffu, sl, j);
                float dsj = __shfl_sync(0xffffffffu, dl, j);
                float4 hs = *((const float4*)(h + (size_t)sj * DF) + lane);
                ax = fmaf(hs.x, dsj, ax);
                ay = fmaf(hs.y, dsj, ay);
                az = fmaf(hs.z, dsj, az);
                aw = fmaf(hs.w, dsj, aw);
            }
        }
        float ox = fmaxf(fmaf(ax, dv, bv.x), 0.f);
        float oy = fmaxf(fmaf(ay, dv, bv.y), 0.f);
        float oz = fmaxf(fmaf(az, dv, bv.z), 0.f);
        float ow = fmaxf(fmaf(aw, dv, bv.w), 0.f);
        *((float4*)(xout + (size_t)v * DF) + lane) = make_float4(ox, oy, oz, ow);
        ls0 += ox; lq0 += ox * ox;
        ls1 += oy; lq1 += oy * oy;
        ls2 += oz; lq2 += oz * oz;
        ls3 += ow; lq3 += ow * ow;
    }
    atomicAdd(&bs[lane * 4 + 0], ls0); atomicAdd(&bq[lane * 4 + 0], lq0);
    atomicAdd(&bs[lane * 4 + 1], ls1); atomicAdd(&bq[lane * 4 + 1], lq1);
    atomicAdd(&bs[lane * 4 + 2], ls2); atomicAdd(&bq[lane * 4 + 2], lq2);
    atomicAdd(&bs[lane * 4 + 3], ls3); atomicAdd(&bq[lane * 4 + 3], lq3);
    __syncthreads();
    if (tid < DF) {
        atomicAdd(&bnsum[tid], bs[tid]);
        atomicAdd(&bnsq[tid],  bq[tid]);
    }
}

// ------------------- global_add_pool -------------------
__global__ void k_pool(const float* __restrict__ x, const int* __restrict__ batch) {
    int lane = threadIdx.x & 31;
    int w    = (blockIdx.x * blockDim.x + threadIdx.x) >> 5;
    int nW   = (gridDim.x * blockDim.x) >> 5;
    int C    = (NN + nW - 1) / nW;
    int beg = w * C;
    int end = beg + C; if (end > NN) end = NN;
    if (beg >= end) return;

    float a0 = 0, a1 = 0, a2 = 0, a3 = 0, cntf = 0;
    int cur = batch[beg];
    for (int v = beg; v < end; v++) {
        int g = batch[v];
        if (g != cur) {
            atomicAdd(&g_pool[cur * DF + lane * 4 + 0], a0);
            atomicAdd(&g_pool[cur * DF + lane * 4 + 1], a1);
            atomicAdd(&g_pool[cur * DF + lane * 4 + 2], a2);
            atomicAdd(&g_pool[cur * DF + lane * 4 + 3], a3);
            if (lane == 0) atomicAdd(&g_gcnt[cur], cntf);
            a0 = a1 = a2 = a3 = 0.f; cntf = 0.f; cur = g;
        }
        float4 xv = *((const float4*)(x + (size_t)v * DF) + lane);
        a0 += xv.x; a1 += xv.y; a2 += xv.z; a3 += xv.w; cntf += 1.f;
    }
    atomicAdd(&g_pool[cur * DF + lane * 4 + 0], a0);
    atomicAdd(&g_pool[cur * DF + lane * 4 + 1], a1);
    atomicAdd(&g_pool[cur * DF + lane * 4 + 2], a2);
    atomicAdd(&g_pool[cur * DF + lane * 4 + 3], a3);
    if (lane == 0) atomicAdd(&g_gcnt[cur], cntf);
}

// ------------------- head (BN affine computed in-block) -------------------
__global__ void __launch_bounds__(256) k_hg0(
    const float* __restrict__ Wh0, const float* __restrict__ bh0,
    const float* __restrict__ bnsum, const float* __restrict__ bnsq,
    const float* __restrict__ gamma, const float* __restrict__ beta) {
    __shared__ float sx[DF];
    int g = blockIdx.x, j = threadIdx.x;
    if (j < DF) {
        const float invN = 1.0f / NN;
        float m   = bnsum[j] * invN;
        float var = bnsq[j] * invN - m * m;
        float a   = gamma[j] * rsqrtf(var + 1e-5f);
        float c   = beta[j] - a * m;
        sx[j] = a * g_pool[g * DF + j] + c * g_gcnt[g];
    }
    __syncthreads();
    float acc = bh0[j];
#pragma unroll 8
    for (int k = 0; k < DF; k++) acc = fmaf(sx[k], Wh0[k * DH + j], acc);
    float v = fmaxf(acc, 0.f);
    g_h0[g * DH + j] = v;
    atomicAdd(&g_sq[j], v);
    atomicAdd(&g_sq[DH + j], v * v);
}
__global__ void __launch_bounds__(256) k_hg1(
    const float* __restrict__ Wh1, const float* __restrict__ bh1,
    const float* __restrict__ gamma, const float* __restrict__ beta) {
    __shared__ float sx[DH];
    int g = blockIdx.x, j = threadIdx.x;
    {
        const float invG = 1.0f / NG;
        float m   = g_sq[j] * invG;
        float var = g_sq[DH + j] * invG - m * m;
        float a   = gamma[j] * rsqrtf(var + 1e-5f);
        float c   = beta[j] - a * m;
        sx[j] = a * g_h0[g * DH + j] + c;
    }
    __syncthreads();
    float acc = bh1[j];
#pragma unroll 8
    for (int k = 0; k < DH; k++) acc = fmaf(sx[k], Wh1[k * DH + j], acc);
    float v = fmaxf(acc, 0.f);
    g_h1[g * DH + j] = v;
    atomicAdd(&g_sq[2 * DH + j], v);
    atomicAdd(&g_sq[3 * DH + j], v * v);
}
__global__ void __launch_bounds__(256) k_final(
    const float* __restrict__ Wout, const float* __restrict__ bout,
    const float* __restrict__ gamma, const float* __restrict__ beta,
    float* __restrict__ out) {
    __shared__ float red[DH];
    int g = blockIdx.x, t = threadIdx.x;
    {
        const float invG = 1.0f / NG;
        float m   = g_sq[2 * DH + t] * invG;
        float var = g_sq[3 * DH + t] * invG - m * m;
        float a   = gamma[t] * rsqrtf(var + 1e-5f);
        float c   = beta[t] - a * m;
        red[t] = (a * g_h1[g * DH + t] + c) * Wout[t];
    }
    __syncthreads();
    for (int o = DH / 2; o > 0; o >>= 1) {
        if (t < o) red[t] += red[t + o];
        __syncthreads();
    }
    if (t == 0) out[g] = red[0] + bout[0];
}

// ------------------- launch -------------------
extern "C" void kernel_launch(void* const* d_in, const int* in_sizes, int n_in,
                              void* d_out, int out_size) {
    const float* x   = (const float*)d_in[0];
    const int*   ei  = (const int*)d_in[1];
    const int*   bat = (const int*)d_in[2];
    const float* Wc  = (const float*)d_in[3];
    const float* bc  = (const float*)d_in[4];
    const float* gc  = (const float*)d_in[5];
    const float* bec = (const float*)d_in[6];
    const float* Wh0 = (const float*)d_in[7];
    const float* bh0 = (const float*)d_in[8];
    const float* gh0 = (const float*)d_in[9];
    const float* beh0= (const float*)d_in[10];
    const float* Wh1 = (const float*)d_in[11];
    const float* bh1 = (const float*)d_in[12];
    const float* gh1 = (const float*)d_in[13];
    const float* beh1= (const float*)d_in[14];
    const float* Wout= (const float*)d_in[15];
    const float* bout= (const float*)d_in[16];
    float* out = (float*)d_out;

    const int* src = ei;
    const int* dst = ei + NE;

    float *p_x, *p_h, *p_dvec, *p_bnsum, *p_bnsq;
    __nv_bfloat16 *p_Whi, *p_Wlo;
    cudaGetSymbolAddress((void**)&p_x,    g_x);
    cudaGetSymbolAddress((void**)&p_h,    g_h);
    cudaGetSymbolAddress((void**)&p_Whi,  g_Whi);
    cudaGetSymbolAddress((void**)&p_Wlo,  g_Wlo);
    cudaGetSymbolAddress((void**)&p_dvec, g_dvec);
    cudaGetSymbolAddress((void**)&p_bnsum,g_bnsum);
    cudaGetSymbolAddress((void**)&p_bnsq, g_bnsq);

    cudaFuncSetAttribute(k_mmagemm, cudaFuncAttributeMaxDynamicSharedMemorySize, SM_TOT);

    static cudaStream_t s_side = nullptr;
    static cudaEvent_t  e_fork = nullptr, e_join = nullptr;
    if (!s_side) {
        cudaStreamCreateWithFlags(&s_side, cudaStreamNonBlocking);
        cudaEventCreateWithFlags(&e_fork, cudaEventDisableTiming);
        cudaEventCreateWithFlags(&e_join, cudaEventDisableTiming);
    }

    const int T = 256;

    // ---- init (main stream), then fork CSR build onto side stream ----
    k_init<<<(INIT_TOT + T - 1) / T, T>>>();
    cudaEventRecord(e_fork, 0);
    cudaStreamWaitEvent(s_side, e_fork, 0);
    k_hist <<<(NE + T - 1) / T, T, 0, s_side>>>(dst);
    k_scanA<<<SB, 256, 0, s_side>>>();
    k_scanB<<<1, 512, 0, s_side>>>();
    k_scanC<<<SB, 256, 0, s_side>>>();
    k_fill <<<(NE + T - 1) / T, T, 0, s_side>>>(src, dst);
    cudaEventRecord(e_join, s_side);

    // ---- main stream: layer-0 wprep + GEMM overlap CSR build ----
    k_wprep<<<65, T>>>(Wc, nullptr, nullptr, nullptr, nullptr);
    k_mmagemm<<<GEMM_GRID, T, SM_TOT>>>(x, p_Whi, p_Wlo, nullptr, p_h, NN);
    cudaStreamWaitEvent(0, e_join, 0);
    k_agg<<<2048, T>>>(p_h, bc, p_x, p_bnsum, p_bnsq);

    // ---- conv layer 1 ----
    k_wprep<<<65, T>>>(Wc + DF * DF, p_bnsum, p_bnsq, gc, bec);
    k_mmagemm<<<GEMM_GRID, T, SM_TOT>>>(p_x, p_Whi, p_Wlo, p_dvec, p_h, NN);
    k_agg<<<2048, T>>>(p_h, bc + DF, p_x, p_bnsum + DF, p_bnsq + DF);

    // ---- conv layer 2 ----
    k_wprep<<<65, T>>>(Wc + 2 * DF * DF, p_bnsum + DF, p_bnsq + DF, gc + DF, bec + DF);
    k_mmagemm<<<GEMM_GRID, T, SM_TOT>>>(p_x, p_Whi, p_Wlo, p_dvec, p_h, NN);
    k_agg<<<2048, T>>>(p_h, bc + 2 * DF, p_x, p_bnsum + 2 * DF, p_bnsq + 2 * DF);

    // ---- pool (wider grid: fill the chip) ----
    k_pool<<<592, T>>>(p_x, bat);

    // ---- head ----
    k_hg0<<<NG, DH>>>(Wh0, bh0, p_bnsum + 2 * DF, p_bnsq + 2 * DF, gc + 2 * DF, bec + 2 * DF);
    k_hg1<<<NG, DH>>>(Wh1, bh1, gh0, beh0);
    k_final<<<NG, DH>>>(Wout, bout, gh1, beh1, out);
}